// round 11
// baseline (speedup 1.0000x reference)
#include <cuda_runtime.h>
#include <cuda_fp16.h>
#include <mma.h>
#include <cstdint>
#include <math.h>

using namespace nvcuda;

#define NND 50000
#define NNDP 50048          // padded to 128
#define NE  800000
#define NP  262144
#define FIN 572
#define C1  256     // H1
#define C2  128     // H2
#define NC  65

// ======================= scratch =======================
__device__ float g_h[(size_t)NND * 512];
__device__ float g_feat[(size_t)NND * C1];
__device__ float g_s[NND * 2];
__device__ float g_d[NND * 2];
__device__ float g_z1[(size_t)NP * C2];
__device__ float g_z2[(size_t)NP * C2];
__device__ float g_sums[512];
__device__ int   g_deg[NND];
__device__ int   g_rowptr[NND + 1];
__device__ int   g_cursor[NND];
__device__ int   g_csr[NE];
// fp16 activation operand arrays (padded rows)
__device__ __half g_xh[(size_t)NNDP * 576];
__device__ __half g_fh[(size_t)NNDP * C1];
__device__ __half g_z1h[(size_t)NP * C2];
__device__ __half g_z2h[(size_t)NP * C2];
// transposed, zero-padded, hi/lo-split fp16 weights [N_pad, kpad]
__device__ __half g_w1th[512 * 576], g_w1tl[512 * 576];
__device__ __half g_w2th[512 * 256], g_w2tl[512 * 256];
__device__ __half g_lw1th[128 * 512], g_lw1tl[128 * 512];
__device__ __half g_lw2th[128 * 128], g_lw2tl[128 * 128];
__device__ __half g_fwth[128 * 128], g_fwtl[128 * 128];

__device__ __forceinline__ float lrelu(float x) { return x > 0.f ? x : 0.2f * x; }

__device__ __forceinline__ void split_w(float v, __half* H, __half* L) {
    __half hi = __float2half(v);
    *H = hi;
    *L = __float2half(v - __half2float(hi));
}

__global__ void zero_i(int* p, int n) {
    int i = blockIdx.x * blockDim.x + threadIdx.x;
    if (i < n) p[i] = 0;
}
__global__ void zero_f(float* p, int n) {
    int i = blockIdx.x * blockDim.x + threadIdx.x;
    if (i < n) p[i] = 0.f;
}

// X [M,K] fp32 -> fp16 [Mpad,kpad] zero padded
__global__ void conv_mat(const float* __restrict__ X, __half* __restrict__ H,
                         int M, int K, int kpad, int total) {
    int i = blockIdx.x * blockDim.x + threadIdx.x;
    if (i >= total) return;
    int row = i / kpad, k = i - row * kpad;
    H[i] = __float2half((row < M && k < K) ? X[(size_t)row * K + k] : 0.f);
}

// Wt[n*kpad+k] = W[k*N+n], split to fp16 hi/lo, zero padded
__global__ void transposeW_split(const float* __restrict__ W, __half* __restrict__ H,
                                 __half* __restrict__ L, int K, int N, int rows,
                                 int kpad) {
    int i = blockIdx.x * blockDim.x + threadIdx.x;
    int tot = rows * kpad;
    if (i >= tot) return;
    int n = i / kpad, k = i - n * kpad;
    float v = (k < K && n < N) ? W[(size_t)k * N + n] : 0.f;
    split_w(v, H + i, L + i);
}

// fused: lw1 + lw2 + fw split-transposes in one launch
__global__ void transposeW_rest(const float* __restrict__ lw1,
                                const float* __restrict__ lw2, const float* __restrict__ fw,
                                __half* __restrict__ H1, __half* __restrict__ L1,
                                __half* __restrict__ H2, __half* __restrict__ L2,
                                __half* __restrict__ HF, __half* __restrict__ LF) {
    int i = blockIdx.x * blockDim.x + threadIdx.x;
    if (i < 128 * 512) {
        int n = i >> 9, k = i & 511;
        split_w(lw1[(size_t)k * C2 + n], H1 + i, L1 + i);
    } else if (i < 128 * 512 + 128 * 128) {
        int j = i - 128 * 512;
        int n = j >> 7, k = j & 127;
        split_w(lw2[(size_t)k * C2 + n], H2 + j, L2 + j);
    } else if (i < 128 * 512 + 2 * 128 * 128) {
        int j = i - 128 * 512 - 128 * 128;
        int n = j >> 7, k = j & 127;
        float v = (n < NC) ? fw[(size_t)k * NC + n] : 0.f;
        split_w(v, HF + j, LF + j);
    }
}

// ======================= CSR build =======================
__global__ void count_deg(const int* __restrict__ ei, int* __restrict__ deg) {
    int e = blockIdx.x * blockDim.x + threadIdx.x;
    if (e < NE) atomicAdd(&deg[ei[NE + e]], 1);
}

__global__ void scan_kernel(const int* __restrict__ deg, int* __restrict__ rowptr,
                            int* __restrict__ cursor) {
    __shared__ int sh[1024];
    __shared__ int carry_s;
    int t = threadIdx.x;
    if (t == 0) { carry_s = 0; rowptr[0] = 0; }
    __syncthreads();
    for (int base = 0; base < NND; base += 1024) {
        int v = (base + t < NND) ? deg[base + t] : 0;
        sh[t] = v;
        __syncthreads();
        for (int off = 1; off < 1024; off <<= 1) {
            int add = (t >= off) ? sh[t - off] : 0;
            __syncthreads();
            sh[t] += add;
            __syncthreads();
        }
        int incl = sh[t];
        int carry = carry_s;
        if (base + t < NND) {
            rowptr[base + t + 1] = carry + incl;
            cursor[base + t]     = carry + incl - v;
        }
        __syncthreads();
        if (t == 1023) carry_s = carry + incl;
        __syncthreads();
    }
}

__global__ void fill_csr(const int* __restrict__ ei, int* __restrict__ cursor,
                         int* __restrict__ csr) {
    int e = blockIdx.x * blockDim.x + threadIdx.x;
    if (e < NE) {
        int dn = ei[NE + e];
        int pos = atomicAdd(&cursor[dn], 1);
        csr[pos] = ei[e];
    }
}

// ======================= fp16x2 (split-B) wmma GEMM, 64x64 warp tiles ======
// C[M,Nc] = A[M,kpad] @ (Bh+Bl)^T.  CTA 128x128, 4 warps (2x2), warp tile
// 64x64, BK=32, cp.async 2-stage. 16 MMA per A-frag-set -> higher
// MMA/fragment-load ratio than 8-warp 64x32.
#define TROW 40                   // padded SMEM row (halves) -> 80 B
#define TILE_B (128 * TROW * 2)   // 10240 B per tile
#define BUF_B  (3 * TILE_B)       // A + Bh + Bl = 30720 B
#define MG_SMEM 65536             // 2 stages (61440) | epilogue 64KB union

__device__ __forceinline__ uint32_t smem_u32(const void* p) {
    uint32_t a;
    asm("{ .reg .u64 t; cvta.to.shared.u64 t, %1; cvt.u32.u64 %0, t; }"
        : "=r"(a) : "l"(p));
    return a;
}
__device__ __forceinline__ void cpa16(void* dst, const void* src) {
    asm volatile("cp.async.cg.shared.global [%0], [%1], 16;"
                 :: "r"(smem_u32(dst)), "l"(src));
}

template <bool GATHER>
__global__ void __launch_bounds__(128, 2) tg_gemm(
    const __half* __restrict__ A,
    const __half* __restrict__ Bh, const __half* __restrict__ Bl,
    const float* __restrict__ bias, float* __restrict__ C,
    int M, int Nc, int kpad, int strideA,
    const int* __restrict__ id0, const int* __restrict__ id1, int baseW) {
    extern __shared__ char sm[];
    __shared__ int sid0[128], sid1[128];
    float* ep = (float*)sm;

    const int tid = threadIdx.x;
    const int wid = tid >> 5;
    const int wm = wid >> 1;     // 0..1
    const int wn = wid & 1;      // 0..1
    const int m0 = blockIdx.y * 128;
    const int n0 = blockIdx.x * 128;
    const int chunks = kpad >> 5;
    const int lr = tid >> 2;     // 0..31
    const int lc = tid & 3;      // 16B slot within 64B row

    if (GATHER) {
        sid0[tid] = id0[m0 + tid];
        sid1[tid] = id1[m0 + tid];
        __syncthreads();
    }

    wmma::fragment<wmma::accumulator, 16, 16, 16, float> acc[4][4];
#pragma unroll
    for (int i = 0; i < 4; i++)
#pragma unroll
        for (int j = 0; j < 4; j++) wmma::fill_fragment(acc[i][j], 0.f);

    auto load_chunk = [&](int kt, int buf) {
        const int k0 = kt << 5;
        char* base = sm + buf * BUF_B;
        int halfsel = 0, kc = k0 + lc * 8;
        if (GATHER) {
            halfsel = (k0 >= baseW) ? 1 : 0;
            kc = k0 - halfsel * baseW + lc * 8;
        }
#pragma unroll
        for (int it = 0; it < 4; it++) {
            int rr = lr + it * 32;
            size_t aoff;
            if (GATHER) {
                int nid = halfsel ? sid1[rr] : sid0[rr];
                aoff = (size_t)nid * strideA + kc;
            } else {
                aoff = (size_t)(m0 + rr) * strideA + kc;
            }
            int dst = rr * (TROW * 2) + lc * 16;
            cpa16(base + dst, A + aoff);
            size_t boff = (size_t)(n0 + rr) * kpad + k0 + lc * 8;
            cpa16(base + TILE_B + dst, Bh + boff);
            cpa16(base + 2 * TILE_B + dst, Bl + boff);
        }
    };

    load_chunk(0, 0);
    asm volatile("cp.async.commit_group;");

    for (int kt = 0; kt < chunks; kt++) {
        if (kt + 1 < chunks) {
            load_chunk(kt + 1, (kt + 1) & 1);
            asm volatile("cp.async.commit_group;");
            asm volatile("cp.async.wait_group 1;");
        } else {
            asm volatile("cp.async.wait_group 0;");
        }
        __syncthreads();
        char* base = sm + (kt & 1) * BUF_B;
        const __half* sA  = (const __half*)(base);
        const __half* sBh = (const __half*)(base + TILE_B);
        const __half* sBl = (const __half*)(base + 2 * TILE_B);
#pragma unroll
        for (int ks = 0; ks < 32; ks += 16) {
            wmma::fragment<wmma::matrix_a, 16, 16, 16, __half, wmma::row_major> fa[4];
#pragma unroll
            for (int i = 0; i < 4; i++)
                wmma::load_matrix_sync(fa[i], sA + (wm * 64 + i * 16) * TROW + ks, TROW);
#pragma unroll
            for (int j = 0; j < 4; j++) {
                wmma::fragment<wmma::matrix_b, 16, 16, 16, __half, wmma::col_major> fbh;
                wmma::load_matrix_sync(fbh, sBh + (wn * 64 + j * 16) * TROW + ks, TROW);
#pragma unroll
                for (int i = 0; i < 4; i++)
                    wmma::mma_sync(acc[i][j], fa[i], fbh, acc[i][j]);
                wmma::fragment<wmma::matrix_b, 16, 16, 16, __half, wmma::col_major> fbl;
                wmma::load_matrix_sync(fbl, sBl + (wn * 64 + j * 16) * TROW + ks, TROW);
#pragma unroll
                for (int i = 0; i < 4; i++)
                    wmma::mma_sync(acc[i][j], fa[i], fbl, acc[i][j]);
            }
        }
        __syncthreads();
    }

    // ---- epilogue: stage in SMEM, guarded global write ----
#pragma unroll
    for (int i = 0; i < 4; i++)
#pragma unroll
        for (int j = 0; j < 4; j++)
            wmma::store_matrix_sync(ep + (wm * 64 + i * 16) * 128 + wn * 64 + j * 16,
                                    acc[i][j], 128, wmma::mem_row_major);
    __syncthreads();
    if ((Nc & 3) == 0) {
#pragma unroll
        for (int t = 0; t < 32; t++) {
            int idx = tid + 128 * t;
            int rr = idx >> 5, cc = idx & 31;
            int row = m0 + rr, col = n0 + cc * 4;
            if (row < M && col < Nc) {
                float4 v = *(float4*)(ep + rr * 128 + cc * 4);
                if (bias) {
                    v.x += bias[col]; v.y += bias[col + 1];
                    v.z += bias[col + 2]; v.w += bias[col + 3];
                }
                *(float4*)(C + (size_t)row * Nc + col) = v;
            }
        }
    } else {
#pragma unroll
        for (int t = 0; t < 128; t++) {
            int idx = tid + 128 * t;
            int rr = idx >> 7, cc = idx & 127;
            int row = m0 + rr, col = n0 + cc;
            if (row < M && col < Nc) {
                float v = ep[rr * 128 + cc];
                if (bias) v += bias[col];
                C[(size_t)row * Nc + col] = v;
            }
        }
    }
}

// ======================= attention logits =======================
__global__ void sdot_kernel(const float* __restrict__ h, const float* __restrict__ a_src,
                            const float* __restrict__ a_dst, float* __restrict__ s,
                            float* __restrict__ d) {
    __shared__ float4 sh[256];
    int n = blockIdx.x, t = threadIdx.x;
    float h0 = h[(size_t)n * 512 + t];
    float h1 = h[(size_t)n * 512 + 256 + t];
    float4 v = make_float4(h0 * a_src[t], h0 * a_dst[t],
                           h1 * a_src[256 + t], h1 * a_dst[256 + t]);
    sh[t] = v;
    __syncthreads();
    for (int o = 128; o > 0; o >>= 1) {
        if (t < o) {
            float4 w = sh[t + o];
            float4 m = sh[t];
            m.x += w.x; m.y += w.y; m.z += w.z; m.w += w.w;
            sh[t] = m;
        }
        __syncthreads();
    }
    if (t == 0) {
        float4 r = sh[0];
        s[2 * n] = r.x; d[2 * n] = r.y; s[2 * n + 1] = r.z; d[2 * n + 1] = r.w;
    }
}

__device__ __forceinline__ float4 f4fma(float4 a, float w, float4 acc) {
    acc.x = fmaf(a.x, w, acc.x); acc.y = fmaf(a.y, w, acc.y);
    acc.z = fmaf(a.z, w, acc.z); acc.w = fmaf(a.w, w, acc.w);
    return acc;
}

// ======================= GAT softmax + aggregation =======================
__global__ void gat_aggregate(const float* __restrict__ h, const float* __restrict__ s,
                              const float* __restrict__ d, const int* __restrict__ rowptr,
                              const int* __restrict__ csr, const float* __restrict__ bias,
                              float* __restrict__ out) {
    int warp = (blockIdx.x * blockDim.x + threadIdx.x) >> 5;
    int lane = threadIdx.x & 31;
    if (warp >= NND) return;
    int n = warp;
    int beg = rowptr[n], end = rowptr[n + 1];
    float d0 = d[2 * n], d1 = d[2 * n + 1];
    float self0 = lrelu(s[2 * n] + d0);
    float self1 = lrelu(s[2 * n + 1] + d1);

    float m0 = self0, m1 = self1;
    for (int i = beg + lane; i < end; i += 32) {
        int src = csr[i];
        m0 = fmaxf(m0, lrelu(s[2 * src] + d0));
        m1 = fmaxf(m1, lrelu(s[2 * src + 1] + d1));
    }
#pragma unroll
    for (int o = 16; o; o >>= 1) {
        m0 = fmaxf(m0, __shfl_xor_sync(0xffffffffu, m0, o));
        m1 = fmaxf(m1, __shfl_xor_sync(0xffffffffu, m1, o));
    }
    float z0 = (lane == 0) ? __expf(self0 - m0) : 0.f;
    float z1 = (lane == 0) ? __expf(self1 - m1) : 0.f;
    for (int i = beg + lane; i < end; i += 32) {
        int src = csr[i];
        z0 += __expf(lrelu(s[2 * src] + d0) - m0);
        z1 += __expf(lrelu(s[2 * src + 1] + d1) - m1);
    }
#pragma unroll
    for (int o = 16; o; o >>= 1) {
        z0 += __shfl_xor_sync(0xffffffffu, z0, o);
        z1 += __shfl_xor_sync(0xffffffffu, z1, o);
    }
    float inv0 = 1.f / (z0 + 1e-16f), inv1 = 1.f / (z1 + 1e-16f);

    const float4* h4 = (const float4*)h;
    float4 a0 = {0, 0, 0, 0}, a1 = a0, a2 = a0, a3 = a0;
    {
        float w0 = __expf(self0 - m0) * inv0;
        float w1 = __expf(self1 - m1) * inv1;
        const float4* row = h4 + (size_t)n * 128;
        a0 = f4fma(row[lane], w0, a0);
        a1 = f4fma(row[lane + 32], w0, a1);
        a2 = f4fma(row[lane + 64], w1, a2);
        a3 = f4fma(row[lane + 96], w1, a3);
    }
    for (int i = beg; i < end; i++) {
        int src = csr[i];
        float w0 = __expf(lrelu(s[2 * src] + d0) - m0) * inv0;
        float w1 = __expf(lrelu(s[2 * src + 1] + d1) - m1) * inv1;
        const float4* row = h4 + (size_t)src * 128;
        a0 = f4fma(row[lane], w0, a0);
        a1 = f4fma(row[lane + 32], w0, a1);
        a2 = f4fma(row[lane + 64], w1, a2);
        a3 = f4fma(row[lane + 96], w1, a3);
    }
    const float4* b4 = (const float4*)bias;
    float4 bA = b4[lane], bB = b4[lane + 32];
    float4 r0, r1;
    r0.x = (a0.x + a2.x) * 0.5f + bA.x; r0.y = (a0.y + a2.y) * 0.5f + bA.y;
    r0.z = (a0.z + a2.z) * 0.5f + bA.z; r0.w = (a0.w + a2.w) * 0.5f + bA.w;
    r1.x = (a1.x + a3.x) * 0.5f + bB.x; r1.y = (a1.y + a3.y) * 0.5f + bB.y;
    r1.z = (a1.z + a3.z) * 0.5f + bB.z; r1.w = (a1.w + a3.w) * 0.5f + bB.w;
    float4* o4 = (float4*)out;
    o4[(size_t)n * 64 + lane] = r0;
    o4[(size_t)n * 64 + lane + 32] = r1;
}

// ======================= batch norm =======================
__global__ void bn_stats(const float* __restrict__ x, float* __restrict__ sums,
                         int rows, int C, int rowsPerBlock) {
    int c = threadIdx.x;
    int r0 = blockIdx.x * rowsPerBlock;
    int r1 = min(rows, r0 + rowsPerBlock);
    float s = 0.f, q = 0.f;
    for (int r = r0; r < r1; r++) {
        float v = x[(size_t)r * C + c];
        s += v;
        q += v * v;
    }
    atomicAdd(&sums[c], s);
    atomicAdd(&sums[C + c], q);
}

// apply BN+relu, emit fp16 (GEMM A-operand form)
__global__ void bn_apply_h(const float* __restrict__ x, const float* __restrict__ sums,
                           const float* __restrict__ g, const float* __restrict__ b,
                           __half* __restrict__ H, int rows, int C) {
    size_t i = (size_t)blockIdx.x * blockDim.x + threadIdx.x;
    if (i >= (size_t)rows * C) return;
    int c = (int)(i % C);
    float mu = sums[c] / rows;
    float var = sums[C + c] / rows - mu * mu;
    float y = g[c] * (x[i] - mu) * rsqrtf(var + 1e-5f) + b[c];
    H[i] = __float2half(fmaxf(y, 0.f));
}

// ======================= launch =======================
extern "C" void kernel_launch(void* const* d_in, const int* in_sizes, int n_in,
                              void* d_out, int out_size) {
    const int*   edge_index = (const int*)d_in[0];
    const float* x      = (const float*)d_in[1];
    const int*   edge_id = (const int*)d_in[2];
    const float* W1     = (const float*)d_in[3];
    const float* a_src1 = (const float*)d_in[4];
    const float* a_dst1 = (const float*)d_in[5];
    const float* b1     = (const float*)d_in[6];
    const float* bn1_g  = (const float*)d_in[7];
    const float* bn1_b  = (const float*)d_in[8];
    const float* W2     = (const float*)d_in[9];
    const float* a_src2 = (const float*)d_in[10];
    const float* a_dst2 = (const float*)d_in[11];
    const float* b2     = (const float*)d_in[12];
    const float* bn2_g  = (const float*)d_in[13];
    const float* bn2_b  = (const float*)d_in[14];
    const float* lw1    = (const float*)d_in[15];
    const float* lb1    = (const float*)d_in[16];
    const float* bn3_g  = (const float*)d_in[17];
    const float* bn3_b  = (const float*)d_in[18];
    const float* lw2    = (const float*)d_in[19];
    const float* lb2    = (const float*)d_in[20];
    const float* bn4_g  = (const float*)d_in[21];
    const float* bn4_b  = (const float*)d_in[22];
    const float* fw     = (const float*)d_in[23];
    const float* fb     = (const float*)d_in[24];
    float* out = (float*)d_out;

    float *h, *feat, *s, *d, *z1, *z2, *sums;
    int *deg, *rowptr, *cursor, *csr;
    __half *xh, *fh, *z1h, *z2h;
    __half *w1th, *w1tl, *w2th, *w2tl, *lw1th, *lw1tl, *lw2th, *lw2tl, *fwth, *fwtl;
    cudaGetSymbolAddress((void**)&h, g_h);
    cudaGetSymbolAddress((void**)&feat, g_feat);
    cudaGetSymbolAddress((void**)&s, g_s);
    cudaGetSymbolAddress((void**)&d, g_d);
    cudaGetSymbolAddress((void**)&z1, g_z1);
    cudaGetSymbolAddress((void**)&z2, g_z2);
    cudaGetSymbolAddress((void**)&sums, g_sums);
    cudaGetSymbolAddress((void**)&deg, g_deg);
    cudaGetSymbolAddress((void**)&rowptr, g_rowptr);
    cudaGetSymbolAddress((void**)&cursor, g_cursor);
    cudaGetSymbolAddress((void**)&csr, g_csr);
    cudaGetSymbolAddress((void**)&xh, g_xh);
    cudaGetSymbolAddress((void**)&fh, g_fh);
    cudaGetSymbolAddress((void**)&z1h, g_z1h);
    cudaGetSymbolAddress((void**)&z2h, g_z2h);
    cudaGetSymbolAddress((void**)&w1th, g_w1th);
    cudaGetSymbolAddress((void**)&w1tl, g_w1tl);
    cudaGetSymbolAddress((void**)&w2th, g_w2th);
    cudaGetSymbolAddress((void**)&w2tl, g_w2tl);
    cudaGetSymbolAddress((void**)&lw1th, g_lw1th);
    cudaGetSymbolAddress((void**)&lw1tl, g_lw1tl);
    cudaGetSymbolAddress((void**)&lw2th, g_lw2th);
    cudaGetSymbolAddress((void**)&lw2tl, g_lw2tl);
    cudaGetSymbolAddress((void**)&fwth, g_fwth);
    cudaGetSymbolAddress((void**)&fwtl, g_fwtl);

    cudaFuncSetAttribute(tg_gemm<false>, cudaFuncAttributeMaxDynamicSharedMemorySize, MG_SMEM);
    cudaFuncSetAttribute(tg_gemm<true>, cudaFuncAttributeMaxDynamicSharedMemorySize, MG_SMEM);

    const int mt_n = NNDP / 128;   // 391
    const int mt_p = NP / 128;     // 2048

    // ---- prep + GEMM1 placed so GEMM1 is launch index 3 (ncu capture slot) ----
    conv_mat<<<((size_t)NNDP * 576 + 255) / 256, 256>>>(x, xh, NND, FIN, 576, NNDP * 576); // 0
    transposeW_split<<<(512 * 576 + 255) / 256, 256>>>(W1, w1th, w1tl, FIN, 512, 512, 576); // 1
    transposeW_split<<<(512 * 256 + 255) / 256, 256>>>(W2, w2th, w2tl, C1, 512, 512, 256);  // 2
    tg_gemm<false><<<dim3(4, mt_n), 128, MG_SMEM>>>(                                        // 3
        xh, w1th, w1tl, nullptr, h, NND, 512, 576, 576, nullptr, nullptr, 0);

    // ---- remaining prep (independent of GEMM1) ----
    transposeW_rest<<<(128 * 512 + 2 * 128 * 128 + 255) / 256, 256>>>(
        lw1, lw2, fw, lw1th, lw1tl, lw2th, lw2tl, fwth, fwtl);

    // ---- CSR build ----
    zero_i<<<(NND + 255) / 256, 256>>>(deg, NND);
    count_deg<<<(NE + 255) / 256, 256>>>(edge_index, deg);
    scan_kernel<<<1, 1024>>>(deg, rowptr, cursor);
    fill_csr<<<(NE + 255) / 256, 256>>>(edge_index, cursor, csr);

    // ---- GAT layer 1 (post-GEMM) ----
    sdot_kernel<<<NND, 256>>>(h, a_src1, a_dst1, s, d);
    gat_aggregate<<<(NND * 32 + 255) / 256, 256>>>(h, s, d, rowptr, csr, b1, feat);
    zero_f<<<2, 256>>>(sums, 512);
    bn_stats<<<(NND + 511) / 512, 256>>>(feat, sums, NND, C1, 512);
    bn_apply_h<<<(int)(((size_t)NND * C1 + 255) / 256), 256>>>(
        feat, sums, bn1_g, bn1_b, fh, NND, C1);

    // ---- GAT layer 2 ----
    tg_gemm<false><<<dim3(4, mt_n), 128, MG_SMEM>>>(
        fh, w2th, w2tl, nullptr, h, NND, 512, 256, 256, nullptr, nullptr, 0);
    sdot_kernel<<<NND, 256>>>(h, a_src2, a_dst2, s, d);
    gat_aggregate<<<(NND * 32 + 255) / 256, 256>>>(h, s, d, rowptr, csr, b2, feat);
    zero_f<<<2, 256>>>(sums, 512);
    bn_stats<<<(NND + 511) / 512, 256>>>(feat, sums, NND, C1, 512);
    bn_apply_h<<<(int)(((size_t)NND * C1 + 255) / 256), 256>>>(
        feat, sums, bn2_g, bn2_b, fh, NND, C1);

    // ---- pair MLP ----
    tg_gemm<true><<<dim3(1, mt_p), 128, MG_SMEM>>>(
        fh, lw1th, lw1tl, lb1, z1, NP, C2, 512, C1, edge_id, edge_id + NP, C1);
    zero_f<<<1, 256>>>(sums, 256);
    bn_stats<<<(NP + 1023) / 1024, C2>>>(z1, sums, NP, C2, 1024);
    bn_apply_h<<<(int)(((size_t)NP * C2 + 255) / 256), 256>>>(
        z1, sums, bn3_g, bn3_b, z1h, NP, C2);

    tg_gemm<false><<<dim3(1, mt_p), 128, MG_SMEM>>>(
        z1h, lw2th, lw2tl, lb2, z2, NP, C2, 128, 128, nullptr, nullptr, 0);
    zero_f<<<1, 256>>>(sums, 256);
    bn_stats<<<(NP + 1023) / 1024, C2>>>(z2, sums, NP, C2, 1024);
    bn_apply_h<<<(int)(((size_t)NP * C2 + 255) / 256), 256>>>(
        z2, sums, bn4_g, bn4_b, z2h, NP, C2);

    tg_gemm<false><<<dim3(1, mt_p), 128, MG_SMEM>>>(
        z2h, fwth, fwtl, fb, out, NP, NC, 128, 128, nullptr, nullptr, 0);
}

// round 13
// speedup vs baseline: 1.4940x; 1.4940x over previous
#include <cuda_runtime.h>
#include <cuda_fp16.h>
#include <mma.h>
#include <cstdint>
#include <math.h>

using namespace nvcuda;

#define NND 50000
#define NNDP 50048          // padded to 128
#define NE  800000
#define NP  262144
#define FIN 572
#define C1  256     // H1
#define C2  128     // H2
#define NC  65

// ======================= scratch =======================
__device__ float g_h[(size_t)NND * 512];      // post-W features fp32
__device__ float g_feat[(size_t)NND * C1];
__device__ float g_s[NND * 2];
__device__ float g_d[NND * 2];
__device__ float g_z1[(size_t)NP * C2];
__device__ float g_z2[(size_t)NP * C2];
__device__ float g_sums[512];
__device__ int   g_deg[NND];
__device__ int   g_rowptr[NND + 1];
__device__ int   g_cursor[NND];
__device__ int   g_csr[NE];
// fp16 activation operand arrays (padded rows)
__device__ __half g_xh[(size_t)NNDP * 576];
__device__ __half g_fh[(size_t)NNDP * C1];
__device__ __half g_z1h[(size_t)NP * C2];
__device__ __half g_z2h[(size_t)NP * C2];
// transposed, zero-padded, hi/lo-split fp16 weights [N_pad, kpad]
__device__ __half g_w1th[512 * 576], g_w1tl[512 * 576];
__device__ __half g_w2th[512 * 256], g_w2tl[512 * 256];
__device__ __half g_lw1th[128 * 512], g_lw1tl[128 * 512];
__device__ __half g_lw2th[128 * 128], g_lw2tl[128 * 128];
__device__ __half g_fwth[128 * 128], g_fwtl[128 * 128];

__device__ __forceinline__ float lrelu(float x) { return x > 0.f ? x : 0.2f * x; }

__device__ __forceinline__ void split_w(float v, __half* H, __half* L) {
    __half hi = __float2half(v);
    *H = hi;
    *L = __float2half(v - __half2float(hi));
}

__global__ void zero_i(int* p, int n) {
    int i = blockIdx.x * blockDim.x + threadIdx.x;
    if (i < n) p[i] = 0;
}
__global__ void zero_f(float* p, int n) {
    int i = blockIdx.x * blockDim.x + threadIdx.x;
    if (i < n) p[i] = 0.f;
}

// X [M,K] fp32 -> fp16 [Mpad,kpad] zero padded; also zeroes s,d (2*NND)
__global__ void conv_mat(const float* __restrict__ X, __half* __restrict__ H,
                         float* __restrict__ s, float* __restrict__ d,
                         int M, int K, int kpad, int total) {
    int i = blockIdx.x * blockDim.x + threadIdx.x;
    if (i >= total) return;
    if (i < 2 * NND) { s[i] = 0.f; d[i] = 0.f; }
    int row = i / kpad, k = i - row * kpad;
    H[i] = __float2half((row < M && k < K) ? X[(size_t)row * K + k] : 0.f);
}

// Wt[n*kpad+k] = W[k*N+n], split to fp16 hi/lo, zero padded
__global__ void transposeW_split(const float* __restrict__ W, __half* __restrict__ H,
                                 __half* __restrict__ L, int K, int N, int rows,
                                 int kpad) {
    int i = blockIdx.x * blockDim.x + threadIdx.x;
    int tot = rows * kpad;
    if (i >= tot) return;
    int n = i / kpad, k = i - n * kpad;
    float v = (k < K && n < N) ? W[(size_t)k * N + n] : 0.f;
    split_w(v, H + i, L + i);
}

// fused: lw1 + lw2 + fw split-transposes in one launch
__global__ void transposeW_rest(const float* __restrict__ lw1,
                                const float* __restrict__ lw2, const float* __restrict__ fw,
                                __half* __restrict__ H1, __half* __restrict__ L1,
                                __half* __restrict__ H2, __half* __restrict__ L2,
                                __half* __restrict__ HF, __half* __restrict__ LF) {
    int i = blockIdx.x * blockDim.x + threadIdx.x;
    if (i < 128 * 512) {
        int n = i >> 9, k = i & 511;
        split_w(lw1[(size_t)k * C2 + n], H1 + i, L1 + i);
    } else if (i < 128 * 512 + 128 * 128) {
        int j = i - 128 * 512;
        int n = j >> 7, k = j & 127;
        split_w(lw2[(size_t)k * C2 + n], H2 + j, L2 + j);
    } else if (i < 128 * 512 + 2 * 128 * 128) {
        int j = i - 128 * 512 - 128 * 128;
        int n = j >> 7, k = j & 127;
        float v = (n < NC) ? fw[(size_t)k * NC + n] : 0.f;
        split_w(v, HF + j, LF + j);
    }
}

// ======================= CSR build =======================
__global__ void count_deg(const int* __restrict__ ei, int* __restrict__ deg) {
    int e = blockIdx.x * blockDim.x + threadIdx.x;
    if (e < NE) atomicAdd(&deg[ei[NE + e]], 1);
}

__global__ void scan_kernel(const int* __restrict__ deg, int* __restrict__ rowptr,
                            int* __restrict__ cursor) {
    __shared__ int sh[1024];
    __shared__ int carry_s;
    int t = threadIdx.x;
    if (t == 0) { carry_s = 0; rowptr[0] = 0; }
    __syncthreads();
    for (int base = 0; base < NND; base += 1024) {
        int v = (base + t < NND) ? deg[base + t] : 0;
        sh[t] = v;
        __syncthreads();
        for (int off = 1; off < 1024; off <<= 1) {
            int add = (t >= off) ? sh[t - off] : 0;
            __syncthreads();
            sh[t] += add;
            __syncthreads();
        }
        int incl = sh[t];
        int carry = carry_s;
        if (base + t < NND) {
            rowptr[base + t + 1] = carry + incl;
            cursor[base + t]     = carry + incl - v;
        }
        __syncthreads();
        if (t == 1023) carry_s = carry + incl;
        __syncthreads();
    }
}

__global__ void fill_csr(const int* __restrict__ ei, int* __restrict__ cursor,
                         int* __restrict__ csr) {
    int e = blockIdx.x * blockDim.x + threadIdx.x;
    if (e < NE) {
        int dn = ei[NE + e];
        int pos = atomicAdd(&cursor[dn], 1);
        csr[pos] = ei[e];
    }
}

// ======================= fp16x2 (split-B) wmma GEMM (R9 shape) =============
// C[M,Nc] = A[M,kpad] @ (Bh+Bl)^T.  CTA 128x128, 8 warps (2x4), warp tile
// 64x32, BK=32, cp.async 2-stage. SDOT: fused attention-logit partial dots
// (each 128-col tile lies in exactly one head).
#define TROW 40                   // padded SMEM row (halves) -> 80 B
#define TILE_B (128 * TROW * 2)   // 10240 B per tile
#define BUF_B  (3 * TILE_B)       // A + Bh + Bl = 30720 B
#define MG_SMEM 65536             // 2 stages (61440) | epilogue 64KB union

__device__ __forceinline__ uint32_t smem_u32(const void* p) {
    uint32_t a;
    asm("{ .reg .u64 t; cvta.to.shared.u64 t, %1; cvt.u32.u64 %0, t; }"
        : "=r"(a) : "l"(p));
    return a;
}
__device__ __forceinline__ void cpa16(void* dst, const void* src) {
    asm volatile("cp.async.cg.shared.global [%0], [%1], 16;"
                 :: "r"(smem_u32(dst)), "l"(src));
}

template <bool GATHER, bool SDOT>
__global__ void __launch_bounds__(256, 2) tg_gemm(
    const __half* __restrict__ A,
    const __half* __restrict__ Bh, const __half* __restrict__ Bl,
    const float* __restrict__ bias, float* __restrict__ C,
    int M, int Nc, int kpad, int strideA,
    const int* __restrict__ id0, const int* __restrict__ id1, int baseW,
    const float* __restrict__ a_src, const float* __restrict__ a_dst,
    float* __restrict__ s, float* __restrict__ d) {
    extern __shared__ char sm[];
    __shared__ int sid0[128], sid1[128];
    float* ep = (float*)sm;

    const int tid = threadIdx.x;
    const int wid = tid >> 5;
    const int wm = wid >> 2;
    const int wn = wid & 3;
    const int m0 = blockIdx.y * 128;
    const int n0 = blockIdx.x * 128;
    const int chunks = kpad >> 5;
    const int lr = tid >> 2;     // 0..63
    const int lc = tid & 3;      // 16B slot

    if (GATHER) {
        if (tid < 128) {
            sid0[tid] = id0[m0 + tid];
            sid1[tid] = id1[m0 + tid];
        }
        __syncthreads();
    }

    wmma::fragment<wmma::accumulator, 16, 16, 16, float> acc[4][2];
#pragma unroll
    for (int i = 0; i < 4; i++)
#pragma unroll
        for (int j = 0; j < 2; j++) wmma::fill_fragment(acc[i][j], 0.f);

    auto load_chunk = [&](int kt, int buf) {
        const int k0 = kt << 5;
        char* base = sm + buf * BUF_B;
        int halfsel = 0, kc = k0 + lc * 8;
        if (GATHER) {
            halfsel = (k0 >= baseW) ? 1 : 0;
            kc = k0 - halfsel * baseW + lc * 8;
        }
#pragma unroll
        for (int it = 0; it < 2; it++) {
            int rr = lr + it * 64;
            size_t aoff;
            if (GATHER) {
                int nid = halfsel ? sid1[rr] : sid0[rr];
                aoff = (size_t)nid * strideA + kc;
            } else {
                aoff = (size_t)(m0 + rr) * strideA + kc;
            }
            int dst = rr * (TROW * 2) + lc * 16;
            cpa16(base + dst, A + aoff);
            size_t boff = (size_t)(n0 + rr) * kpad + k0 + lc * 8;
            cpa16(base + TILE_B + dst, Bh + boff);
            cpa16(base + 2 * TILE_B + dst, Bl + boff);
        }
    };

    load_chunk(0, 0);
    asm volatile("cp.async.commit_group;");

    for (int kt = 0; kt < chunks; kt++) {
        if (kt + 1 < chunks) {
            load_chunk(kt + 1, (kt + 1) & 1);
            asm volatile("cp.async.commit_group;");
            asm volatile("cp.async.wait_group 1;");
        } else {
            asm volatile("cp.async.wait_group 0;");
        }
        __syncthreads();
        char* base = sm + (kt & 1) * BUF_B;
        const __half* sA  = (const __half*)(base);
        const __half* sBh = (const __half*)(base + TILE_B);
        const __half* sBl = (const __half*)(base + 2 * TILE_B);
#pragma unroll
        for (int ks = 0; ks < 32; ks += 16) {
            wmma::fragment<wmma::matrix_a, 16, 16, 16, __half, wmma::row_major> fa[4];
#pragma unroll
            for (int i = 0; i < 4; i++)
                wmma::load_matrix_sync(fa[i], sA + (wm * 64 + i * 16) * TROW + ks, TROW);
#pragma unroll
            for (int j = 0; j < 2; j++) {
                wmma::fragment<wmma::matrix_b, 16, 16, 16, __half, wmma::col_major> fbh, fbl;
                wmma::load_matrix_sync(fbh, sBh + (wn * 32 + j * 16) * TROW + ks, TROW);
                wmma::load_matrix_sync(fbl, sBl + (wn * 32 + j * 16) * TROW + ks, TROW);
#pragma unroll
                for (int i = 0; i < 4; i++) {
                    wmma::mma_sync(acc[i][j], fa[i], fbh, acc[i][j]);
                    wmma::mma_sync(acc[i][j], fa[i], fbl, acc[i][j]);
                }
            }
        }
        __syncthreads();
    }

    // ---- epilogue: stage in SMEM, guarded global write ----
#pragma unroll
    for (int i = 0; i < 4; i++)
#pragma unroll
        for (int j = 0; j < 2; j++)
            wmma::store_matrix_sync(ep + (wm * 64 + i * 16) * 128 + wn * 32 + j * 16,
                                    acc[i][j], 128, wmma::mem_row_major);
    __syncthreads();
    if ((Nc & 3) == 0) {
#pragma unroll
        for (int t = 0; t < 16; t++) {
            int idx = tid + 256 * t;
            int rr = idx >> 5, cc = idx & 31;
            int row = m0 + rr, col = n0 + cc * 4;
            if (row < M && col < Nc) {
                float4 v = *(float4*)(ep + rr * 128 + cc * 4);
                if (bias) {
                    v.x += bias[col]; v.y += bias[col + 1];
                    v.z += bias[col + 2]; v.w += bias[col + 3];
                }
                *(float4*)(C + (size_t)row * Nc + col) = v;
            }
        }
    } else {
#pragma unroll
        for (int t = 0; t < 64; t++) {
            int idx = tid + 256 * t;
            int rr = idx >> 7, cc = idx & 127;
            int row = m0 + rr, col = n0 + cc;
            if (row < M && col < Nc) {
                float v = ep[rr * 128 + cc];
                if (bias) v += bias[col];
                C[(size_t)row * Nc + col] = v;
            }
        }
    }
    if (SDOT) {
        // fused attention-logit partials: this 128-col tile is in one head
        const int lane = tid & 31;
        const int head = (n0 >= 256) ? 1 : 0;
        const int cb = n0 & 255;
        float as[4], ad[4];
#pragma unroll
        for (int k = 0; k < 4; k++) {
            as[k] = a_src[head * 256 + cb + lane * 4 + k];
            ad[k] = a_dst[head * 256 + cb + lane * 4 + k];
        }
        for (int r = wid * 16; r < wid * 16 + 16; r++) {
            int row = m0 + r;
            if (row < M) {
                const float* rp = ep + r * 128 + lane * 4;
                float sv = 0.f, dv = 0.f;
#pragma unroll
                for (int k = 0; k < 4; k++) {
                    sv = fmaf(rp[k], as[k], sv);
                    dv = fmaf(rp[k], ad[k], dv);
                }
#pragma unroll
                for (int o = 16; o; o >>= 1) {
                    sv += __shfl_xor_sync(0xffffffffu, sv, o);
                    dv += __shfl_xor_sync(0xffffffffu, dv, o);
                }
                if (lane == 0) {
                    atomicAdd(&s[2 * row + head], sv);
                    atomicAdd(&d[2 * row + head], dv);
                }
            }
        }
    }
}

__device__ __forceinline__ float4 f4fma(float4 a, float w, float4 acc) {
    acc.x = fmaf(a.x, w, acc.x); acc.y = fmaf(a.y, w, acc.y);
    acc.z = fmaf(a.z, w, acc.z); acc.w = fmaf(a.w, w, acc.w);
    return acc;
}

// ======================= GAT aggregation: fused online softmax =============
__global__ void gat_aggregate(const float* __restrict__ h, const float* __restrict__ s,
                              const float* __restrict__ d, const int* __restrict__ rowptr,
                              const int* __restrict__ csr, const float* __restrict__ bias,
                              float* __restrict__ out) {
    int warp = (blockIdx.x * blockDim.x + threadIdx.x) >> 5;
    int lane = threadIdx.x & 31;
    if (warp >= NND) return;
    int n = warp;
    int beg = rowptr[n], end = rowptr[n + 1];
    float d0 = d[2 * n], d1 = d[2 * n + 1];
    float self0 = lrelu(s[2 * n] + d0);
    float self1 = lrelu(s[2 * n + 1] + d1);

    // fused max+sum (online softmax); lane 0 seeds the self-loop term
    float m0 = self0, z0 = 1.f, m1 = self1, z1 = 1.f;
    if (lane != 0) { m0 = -3.4e38f; z0 = 0.f; m1 = -3.4e38f; z1 = 0.f; }
    for (int i = beg + lane; i < end; i += 32) {
        int src = csr[i];
        float a0v = lrelu(s[2 * src] + d0);
        float a1v = lrelu(s[2 * src + 1] + d1);
        float mn0 = fmaxf(m0, a0v);
        z0 = z0 * __expf(m0 - mn0) + __expf(a0v - mn0);
        m0 = mn0;
        float mn1 = fmaxf(m1, a1v);
        z1 = z1 * __expf(m1 - mn1) + __expf(a1v - mn1);
        m1 = mn1;
    }
#pragma unroll
    for (int o = 16; o; o >>= 1) {
        float mo0 = __shfl_xor_sync(0xffffffffu, m0, o);
        float zo0 = __shfl_xor_sync(0xffffffffu, z0, o);
        float mn0 = fmaxf(m0, mo0);
        z0 = z0 * __expf(m0 - mn0) + zo0 * __expf(mo0 - mn0);
        m0 = mn0;
        float mo1 = __shfl_xor_sync(0xffffffffu, m1, o);
        float zo1 = __shfl_xor_sync(0xffffffffu, z1, o);
        float mn1 = fmaxf(m1, mo1);
        z1 = z1 * __expf(m1 - mn1) + zo1 * __expf(mo1 - mn1);
        m1 = mn1;
    }
    float inv0 = 1.f / (z0 + 1e-16f), inv1 = 1.f / (z1 + 1e-16f);

    // weighted accumulate over 512 channels (lane holds 4x float4)
    const float4* h4 = (const float4*)h;
    float4 a0 = {0, 0, 0, 0}, a1 = a0, a2 = a0, a3 = a0;
    {
        float w0 = __expf(self0 - m0) * inv0;
        float w1 = __expf(self1 - m1) * inv1;
        const float4* row = h4 + (size_t)n * 128;
        a0 = f4fma(row[lane], w0, a0);
        a1 = f4fma(row[lane + 32], w0, a1);
        a2 = f4fma(row[lane + 64], w1, a2);
        a3 = f4fma(row[lane + 96], w1, a3);
    }
    for (int i = beg; i < end; i++) {
        int src = csr[i];  // uniform across warp -> broadcast
        float w0 = __expf(lrelu(s[2 * src] + d0) - m0) * inv0;
        float w1 = __expf(lrelu(s[2 * src + 1] + d1) - m1) * inv1;
        const float4* row = h4 + (size_t)src * 128;
        a0 = f4fma(row[lane], w0, a0);
        a1 = f4fma(row[lane + 32], w0, a1);
        a2 = f4fma(row[lane + 64], w1, a2);
        a3 = f4fma(row[lane + 96], w1, a3);
    }
    const float4* b4 = (const float4*)bias;
    float4 bA = b4[lane], bB = b4[lane + 32];
    float4 r0, r1;
    r0.x = (a0.x + a2.x) * 0.5f + bA.x; r0.y = (a0.y + a2.y) * 0.5f + bA.y;
    r0.z = (a0.z + a2.z) * 0.5f + bA.z; r0.w = (a0.w + a2.w) * 0.5f + bA.w;
    r1.x = (a1.x + a3.x) * 0.5f + bB.x; r1.y = (a1.y + a3.y) * 0.5f + bB.y;
    r1.z = (a1.z + a3.z) * 0.5f + bB.z; r1.w = (a1.w + a3.w) * 0.5f + bB.w;
    float4* o4 = (float4*)out;
    o4[(size_t)n * 64 + lane] = r0;
    o4[(size_t)n * 64 + lane + 32] = r1;
}

// ======================= batch norm =======================
__global__ void bn_stats(const float* __restrict__ x, float* __restrict__ sums,
                         int rows, int C, int rowsPerBlock) {
    int c = threadIdx.x;
    int r0 = blockIdx.x * rowsPerBlock;
    int r1 = min(rows, r0 + rowsPerBlock);
    float s = 0.f, q = 0.f;
    for (int r = r0; r < r1; r++) {
        float v = x[(size_t)r * C + c];
        s += v;
        q += v * v;
    }
    atomicAdd(&sums[c], s);
    atomicAdd(&sums[C + c], q);
}

// apply BN+relu, emit fp16 (GEMM A-operand form); optionally zero s,d
__global__ void bn_apply_h(const float* __restrict__ x, const float* __restrict__ sums,
                           const float* __restrict__ g, const float* __restrict__ b,
                           __half* __restrict__ H, int rows, int C,
                           float* __restrict__ sz, float* __restrict__ dz) {
    size_t i = (size_t)blockIdx.x * blockDim.x + threadIdx.x;
    if (i >= (size_t)rows * C) return;
    if (sz && i < 2 * NND) { sz[i] = 0.f; dz[i] = 0.f; }
    int c = (int)(i % C);
    float mu = sums[c] / rows;
    float var = sums[C + c] / rows - mu * mu;
    float y = g[c] * (x[i] - mu) * rsqrtf(var + 1e-5f) + b[c];
    H[i] = __float2half(fmaxf(y, 0.f));
}

// ======================= launch =======================
extern "C" void kernel_launch(void* const* d_in, const int* in_sizes, int n_in,
                              void* d_out, int out_size) {
    const int*   edge_index = (const int*)d_in[0];
    const float* x      = (const float*)d_in[1];
    const int*   edge_id = (const int*)d_in[2];
    const float* W1     = (const float*)d_in[3];
    const float* a_src1 = (const float*)d_in[4];
    const float* a_dst1 = (const float*)d_in[5];
    const float* b1     = (const float*)d_in[6];
    const float* bn1_g  = (const float*)d_in[7];
    const float* bn1_b  = (const float*)d_in[8];
    const float* W2     = (const float*)d_in[9];
    const float* a_src2 = (const float*)d_in[10];
    const float* a_dst2 = (const float*)d_in[11];
    const float* b2     = (const float*)d_in[12];
    const float* bn2_g  = (const float*)d_in[13];
    const float* bn2_b  = (const float*)d_in[14];
    const float* lw1    = (const float*)d_in[15];
    const float* lb1    = (const float*)d_in[16];
    const float* bn3_g  = (const float*)d_in[17];
    const float* bn3_b  = (const float*)d_in[18];
    const float* lw2    = (const float*)d_in[19];
    const float* lb2    = (const float*)d_in[20];
    const float* bn4_g  = (const float*)d_in[21];
    const float* bn4_b  = (const float*)d_in[22];
    const float* fw     = (const float*)d_in[23];
    const float* fb     = (const float*)d_in[24];
    float* out = (float*)d_out;

    float *h, *feat, *s, *d, *z1, *z2, *sums;
    int *deg, *rowptr, *cursor, *csr;
    __half *xh, *fh, *z1h, *z2h;
    __half *w1th, *w1tl, *w2th, *w2tl, *lw1th, *lw1tl, *lw2th, *lw2tl, *fwth, *fwtl;
    cudaGetSymbolAddress((void**)&h, g_h);
    cudaGetSymbolAddress((void**)&feat, g_feat);
    cudaGetSymbolAddress((void**)&s, g_s);
    cudaGetSymbolAddress((void**)&d, g_d);
    cudaGetSymbolAddress((void**)&z1, g_z1);
    cudaGetSymbolAddress((void**)&z2, g_z2);
    cudaGetSymbolAddress((void**)&sums, g_sums);
    cudaGetSymbolAddress((void**)&deg, g_deg);
    cudaGetSymbolAddress((void**)&rowptr, g_rowptr);
    cudaGetSymbolAddress((void**)&cursor, g_cursor);
    cudaGetSymbolAddress((void**)&csr, g_csr);
    cudaGetSymbolAddress((void**)&xh, g_xh);
    cudaGetSymbolAddress((void**)&fh, g_fh);
    cudaGetSymbolAddress((void**)&z1h, g_z1h);
    cudaGetSymbolAddress((void**)&z2h, g_z2h);
    cudaGetSymbolAddress((void**)&w1th, g_w1th);
    cudaGetSymbolAddress((void**)&w1tl, g_w1tl);
    cudaGetSymbolAddress((void**)&w2th, g_w2th);
    cudaGetSymbolAddress((void**)&w2tl, g_w2tl);
    cudaGetSymbolAddress((void**)&lw1th, g_lw1th);
    cudaGetSymbolAddress((void**)&lw1tl, g_lw1tl);
    cudaGetSymbolAddress((void**)&lw2th, g_lw2th);
    cudaGetSymbolAddress((void**)&lw2tl, g_lw2tl);
    cudaGetSymbolAddress((void**)&fwth, g_fwth);
    cudaGetSymbolAddress((void**)&fwtl, g_fwtl);

    cudaFuncSetAttribute(tg_gemm<false, true>, cudaFuncAttributeMaxDynamicSharedMemorySize, MG_SMEM);
    cudaFuncSetAttribute(tg_gemm<false, false>, cudaFuncAttributeMaxDynamicSharedMemorySize, MG_SMEM);
    cudaFuncSetAttribute(tg_gemm<true, false>, cudaFuncAttributeMaxDynamicSharedMemorySize, MG_SMEM);

    const int mt_n = NNDP / 128;   // 391
    const int mt_p = NP / 128;     // 2048

    // ---- prep + GEMM1 placed so GEMM1 is launch index 3 (ncu capture slot) ----
    conv_mat<<<((size_t)NNDP * 576 + 255) / 256, 256>>>(x, xh, s, d, NND, FIN, 576,
                                                        NNDP * 576);                       // 0
    transposeW_split<<<(512 * 576 + 255) / 256, 256>>>(W1, w1th, w1tl, FIN, 512, 512, 576); // 1
    transposeW_split<<<(512 * 256 + 255) / 256, 256>>>(W2, w2th, w2tl, C1, 512, 512, 256);  // 2
    tg_gemm<false, true><<<dim3(4, mt_n), 256, MG_SMEM>>>(                                  // 3
        xh, w1th, w1tl, nullptr, h, NND, 512, 576, 576, nullptr, nullptr, 0,
        a_src1, a_dst1, s, d);

    // ---- remaining prep (independent of GEMM1) ----
    transposeW_rest<<<(128 * 512 + 2 * 128 * 128 + 255) / 256, 256>>>(
        lw1, lw2, fw, lw1th, lw1tl, lw2th, lw2tl, fwth, fwtl);

    // ---- CSR build ----
    zero_i<<<(NND + 255) / 256, 256>>>(deg, NND);
    count_deg<<<(NE + 255) / 256, 256>>>(edge_index, deg);
    scan_kernel<<<1, 1024>>>(deg, rowptr, cursor);
    fill_csr<<<(NE + 255) / 256, 256>>>(edge_index, cursor, csr);

    // ---- GAT layer 1 (sdot fused into GEMM) ----
    gat_aggregate<<<(NND * 32 + 255) / 256, 256>>>(h, s, d, rowptr, csr, b1, feat);
    zero_f<<<2, 256>>>(sums, 512);
    bn_stats<<<(NND + 511) / 512, 256>>>(feat, sums, NND, C1, 512);
    bn_apply_h<<<(int)(((size_t)NND * C1 + 255) / 256), 256>>>(
        feat, sums, bn1_g, bn1_b, fh, NND, C1, s, d);   // also re-zeroes s,d for layer 2

    // ---- GAT layer 2 ----
    tg_gemm<false, true><<<dim3(4, mt_n), 256, MG_SMEM>>>(
        fh, w2th, w2tl, nullptr, h, NND, 512, 256, 256, nullptr, nullptr, 0,
        a_src2, a_dst2, s, d);
    gat_aggregate<<<(NND * 32 + 255) / 256, 256>>>(h, s, d, rowptr, csr, b2, feat);
    zero_f<<<2, 256>>>(sums, 512);
    bn_stats<<<(NND + 511) / 512, 256>>>(feat, sums, NND, C1, 512);
    bn_apply_h<<<(int)(((size_t)NND * C1 + 255) / 256), 256>>>(
        feat, sums, bn2_g, bn2_b, fh, NND, C1, nullptr, nullptr);

    // ---- pair MLP ----
    tg_gemm<true, false><<<dim3(1, mt_p), 256, MG_SMEM>>>(
        fh, lw1th, lw1tl, lb1, z1, NP, C2, 512, C1, edge_id, edge_id + NP, C1,
        nullptr, nullptr, nullptr, nullptr);
    zero_f<<<1, 256>>>(sums, 256);
    bn_stats<<<(NP + 1023) / 1024, C2>>>(z1, sums, NP, C2, 1024);
    bn_apply_h<<<(int)(((size_t)NP * C2 + 255) / 256), 256>>>(
        z1, sums, bn3_g, bn3_b, z1h, NP, C2, nullptr, nullptr);

    tg_gemm<false, false><<<dim3(1, mt_p), 256, MG_SMEM>>>(
        z1h, lw2th, lw2tl, lb2, z2, NP, C2, 128, 128, nullptr, nullptr, 0,
        nullptr, nullptr, nullptr, nullptr);
    zero_f<<<1, 256>>>(sums, 256);
    bn_stats<<<(NP + 1023) / 1024, C2>>>(z2, sums, NP, C2, 1024);
    bn_apply_h<<<(int)(((size_t)NP * C2 + 255) / 256), 256>>>(
        z2, sums, bn4_g, bn4_b, z2h, NP, C2, nullptr, nullptr);

    tg_gemm<false, false><<<dim3(1, mt_p), 256, MG_SMEM>>>(
        z2h, fwth, fwtl, fb, out, NP, NC, 128, 128, nullptr, nullptr, 0,
        nullptr, nullptr, nullptr, nullptr);
}

// round 15
// speedup vs baseline: 1.5834x; 1.0598x over previous
#include <cuda_runtime.h>
#include <cuda_fp16.h>
#include <mma.h>
#include <cstdint>
#include <math.h>

using namespace nvcuda;

#define NND 50000
#define NNDP 50048          // padded to 128
#define NE  800000
#define NP  262144
#define FIN 572
#define C1  256     // H1
#define C2  128     // H2
#define NC  65

// ======================= scratch =======================
__device__ float g_h[(size_t)NND * 512];      // post-W features fp32
__device__ float g_feat[(size_t)NND * C1];
__device__ float g_s[NND * 2];
__device__ float g_d[NND * 2];
__device__ float g_z1[(size_t)NP * C2];
__device__ float g_z2[(size_t)NP * C2];
__device__ float g_sums[512];
__device__ float g_gw[2 * NE];                // per-edge normalized weights (2 heads)
__device__ float g_selfw[2 * NND];            // per-node self-loop weights
__device__ int   g_deg[NND];
__device__ int   g_rowptr[NND + 1];
__device__ int   g_cursor[NND];
__device__ int   g_csr[NE];
// fp16 activation operand arrays (padded rows)
__device__ __half g_xh[(size_t)NNDP * 576];
__device__ __half g_fh[(size_t)NNDP * C1];
__device__ __half g_z1h[(size_t)NP * C2];
__device__ __half g_z2h[(size_t)NP * C2];
// transposed, zero-padded, hi/lo-split fp16 weights [N_pad, kpad]
__device__ __half g_w1th[512 * 576], g_w1tl[512 * 576];
__device__ __half g_w2th[512 * 256], g_w2tl[512 * 256];
__device__ __half g_lw1th[128 * 512], g_lw1tl[128 * 512];
__device__ __half g_lw2th[128 * 128], g_lw2tl[128 * 128];
__device__ __half g_fwth[128 * 128], g_fwtl[128 * 128];

__device__ __forceinline__ float lrelu(float x) { return x > 0.f ? x : 0.2f * x; }

__device__ __forceinline__ void split_w(float v, __half* H, __half* L) {
    __half hi = __float2half(v);
    *H = hi;
    *L = __float2half(v - __half2float(hi));
}

__global__ void zero_i(int* p, int n) {
    int i = blockIdx.x * blockDim.x + threadIdx.x;
    if (i < n) p[i] = 0;
}
__global__ void zero_f(float* p, int n) {
    int i = blockIdx.x * blockDim.x + threadIdx.x;
    if (i < n) p[i] = 0.f;
}

// X [M,K] fp32 -> fp16 [Mpad,kpad] zero padded; also zeroes s,d (2*NND)
__global__ void conv_mat(const float* __restrict__ X, __half* __restrict__ H,
                         float* __restrict__ s, float* __restrict__ d,
                         int M, int K, int kpad, int total) {
    int i = blockIdx.x * blockDim.x + threadIdx.x;
    if (i >= total) return;
    if (i < 2 * NND) { s[i] = 0.f; d[i] = 0.f; }
    int row = i / kpad, k = i - row * kpad;
    H[i] = __float2half((row < M && k < K) ? X[(size_t)row * K + k] : 0.f);
}

// Wt[n*kpad+k] = W[k*N+n], split to fp16 hi/lo, zero padded
__global__ void transposeW_split(const float* __restrict__ W, __half* __restrict__ H,
                                 __half* __restrict__ L, int K, int N, int rows,
                                 int kpad) {
    int i = blockIdx.x * blockDim.x + threadIdx.x;
    int tot = rows * kpad;
    if (i >= tot) return;
    int n = i / kpad, k = i - n * kpad;
    float v = (k < K && n < N) ? W[(size_t)k * N + n] : 0.f;
    split_w(v, H + i, L + i);
}

// fused: lw1 + lw2 + fw split-transposes in one launch
__global__ void transposeW_rest(const float* __restrict__ lw1,
                                const float* __restrict__ lw2, const float* __restrict__ fw,
                                __half* __restrict__ H1, __half* __restrict__ L1,
                                __half* __restrict__ H2, __half* __restrict__ L2,
                                __half* __restrict__ HF, __half* __restrict__ LF) {
    int i = blockIdx.x * blockDim.x + threadIdx.x;
    if (i < 128 * 512) {
        int n = i >> 9, k = i & 511;
        split_w(lw1[(size_t)k * C2 + n], H1 + i, L1 + i);
    } else if (i < 128 * 512 + 128 * 128) {
        int j = i - 128 * 512;
        int n = j >> 7, k = j & 127;
        split_w(lw2[(size_t)k * C2 + n], H2 + j, L2 + j);
    } else if (i < 128 * 512 + 2 * 128 * 128) {
        int j = i - 128 * 512 - 128 * 128;
        int n = j >> 7, k = j & 127;
        float v = (n < NC) ? fw[(size_t)k * NC + n] : 0.f;
        split_w(v, HF + j, LF + j);
    }
}

// ======================= CSR build =======================
__global__ void count_deg(const int* __restrict__ ei, int* __restrict__ deg) {
    int e = blockIdx.x * blockDim.x + threadIdx.x;
    if (e < NE) atomicAdd(&deg[ei[NE + e]], 1);
}

__global__ void scan_kernel(const int* __restrict__ deg, int* __restrict__ rowptr,
                            int* __restrict__ cursor) {
    __shared__ int sh[1024];
    __shared__ int carry_s;
    int t = threadIdx.x;
    if (t == 0) { carry_s = 0; rowptr[0] = 0; }
    __syncthreads();
    for (int base = 0; base < NND; base += 1024) {
        int v = (base + t < NND) ? deg[base + t] : 0;
        sh[t] = v;
        __syncthreads();
        for (int off = 1; off < 1024; off <<= 1) {
            int add = (t >= off) ? sh[t - off] : 0;
            __syncthreads();
            sh[t] += add;
            __syncthreads();
        }
        int incl = sh[t];
        int carry = carry_s;
        if (base + t < NND) {
            rowptr[base + t + 1] = carry + incl;
            cursor[base + t]     = carry + incl - v;
        }
        __syncthreads();
        if (t == 1023) carry_s = carry + incl;
        __syncthreads();
    }
}

__global__ void fill_csr(const int* __restrict__ ei, int* __restrict__ cursor,
                         int* __restrict__ csr) {
    int e = blockIdx.x * blockDim.x + threadIdx.x;
    if (e < NE) {
        int dn = ei[NE + e];
        int pos = atomicAdd(&cursor[dn], 1);
        csr[pos] = ei[e];
    }
}

// ======================= fp16x2 (split-B) wmma GEMM =============
// CTA 128x128, 8 warps (2x4), warp tile 64x32, BK=32, cp.async 2-stage.
// SDOT: fused attention-logit partial dots. STATS: fused BN column stats
// (requires Nc==128, grid.x==1, M multiple of 128).
#define TROW 40                   // padded SMEM row (halves) -> 80 B
#define TILE_B (128 * TROW * 2)   // 10240 B per tile
#define BUF_B  (3 * TILE_B)       // A + Bh + Bl = 30720 B
#define MG_SMEM 65536             // 2 stages (61440) | epilogue 64KB union

__device__ __forceinline__ uint32_t smem_u32(const void* p) {
    uint32_t a;
    asm("{ .reg .u64 t; cvta.to.shared.u64 t, %1; cvt.u32.u64 %0, t; }"
        : "=r"(a) : "l"(p));
    return a;
}
__device__ __forceinline__ void cpa16(void* dst, const void* src) {
    asm volatile("cp.async.cg.shared.global [%0], [%1], 16;"
                 :: "r"(smem_u32(dst)), "l"(src));
}

template <bool GATHER, bool SDOT, bool STATS>
__global__ void __launch_bounds__(256, 2) tg_gemm(
    const __half* __restrict__ A,
    const __half* __restrict__ Bh, const __half* __restrict__ Bl,
    const float* __restrict__ bias, float* __restrict__ C,
    int M, int Nc, int kpad, int strideA,
    const int* __restrict__ id0, const int* __restrict__ id1, int baseW,
    const float* __restrict__ a_src, const float* __restrict__ a_dst,
    float* __restrict__ s, float* __restrict__ d,
    float* __restrict__ sums) {
    extern __shared__ char sm[];
    __shared__ int sid0[128], sid1[128];
    float* ep = (float*)sm;

    const int tid = threadIdx.x;
    const int wid = tid >> 5;
    const int wm = wid >> 2;
    const int wn = wid & 3;
    const int m0 = blockIdx.y * 128;
    const int n0 = blockIdx.x * 128;
    const int chunks = kpad >> 5;
    const int lr = tid >> 2;     // 0..63
    const int lc = tid & 3;      // 16B slot

    if (GATHER) {
        if (tid < 128) {
            sid0[tid] = id0[m0 + tid];
            sid1[tid] = id1[m0 + tid];
        }
        __syncthreads();
    }

    wmma::fragment<wmma::accumulator, 16, 16, 16, float> acc[4][2];
#pragma unroll
    for (int i = 0; i < 4; i++)
#pragma unroll
        for (int j = 0; j < 2; j++) wmma::fill_fragment(acc[i][j], 0.f);

    auto load_chunk = [&](int kt, int buf) {
        const int k0 = kt << 5;
        char* base = sm + buf * BUF_B;
        int halfsel = 0, kc = k0 + lc * 8;
        if (GATHER) {
            halfsel = (k0 >= baseW) ? 1 : 0;
            kc = k0 - halfsel * baseW + lc * 8;
        }
#pragma unroll
        for (int it = 0; it < 2; it++) {
            int rr = lr + it * 64;
            size_t aoff;
            if (GATHER) {
                int nid = halfsel ? sid1[rr] : sid0[rr];
                aoff = (size_t)nid * strideA + kc;
            } else {
                aoff = (size_t)(m0 + rr) * strideA + kc;
            }
            int dst = rr * (TROW * 2) + lc * 16;
            cpa16(base + dst, A + aoff);
            size_t boff = (size_t)(n0 + rr) * kpad + k0 + lc * 8;
            cpa16(base + TILE_B + dst, Bh + boff);
            cpa16(base + 2 * TILE_B + dst, Bl + boff);
        }
    };

    load_chunk(0, 0);
    asm volatile("cp.async.commit_group;");

    for (int kt = 0; kt < chunks; kt++) {
        if (kt + 1 < chunks) {
            load_chunk(kt + 1, (kt + 1) & 1);
            asm volatile("cp.async.commit_group;");
            asm volatile("cp.async.wait_group 1;");
        } else {
            asm volatile("cp.async.wait_group 0;");
        }
        __syncthreads();
        char* base = sm + (kt & 1) * BUF_B;
        const __half* sA  = (const __half*)(base);
        const __half* sBh = (const __half*)(base + TILE_B);
        const __half* sBl = (const __half*)(base + 2 * TILE_B);
#pragma unroll
        for (int ks = 0; ks < 32; ks += 16) {
            wmma::fragment<wmma::matrix_a, 16, 16, 16, __half, wmma::row_major> fa[4];
#pragma unroll
            for (int i = 0; i < 4; i++)
                wmma::load_matrix_sync(fa[i], sA + (wm * 64 + i * 16) * TROW + ks, TROW);
#pragma unroll
            for (int j = 0; j < 2; j++) {
                wmma::fragment<wmma::matrix_b, 16, 16, 16, __half, wmma::col_major> fbh, fbl;
                wmma::load_matrix_sync(fbh, sBh + (wn * 32 + j * 16) * TROW + ks, TROW);
                wmma::load_matrix_sync(fbl, sBl + (wn * 32 + j * 16) * TROW + ks, TROW);
#pragma unroll
                for (int i = 0; i < 4; i++) {
                    wmma::mma_sync(acc[i][j], fa[i], fbh, acc[i][j]);
                    wmma::mma_sync(acc[i][j], fa[i], fbl, acc[i][j]);
                }
            }
        }
        __syncthreads();
    }

    // ---- epilogue: stage in SMEM, guarded global write ----
#pragma unroll
    for (int i = 0; i < 4; i++)
#pragma unroll
        for (int j = 0; j < 2; j++)
            wmma::store_matrix_sync(ep + (wm * 64 + i * 16) * 128 + wn * 32 + j * 16,
                                    acc[i][j], 128, wmma::mem_row_major);
    __syncthreads();
    float ls[4] = {0, 0, 0, 0}, lq[4] = {0, 0, 0, 0};
    if ((Nc & 3) == 0) {
#pragma unroll
        for (int t = 0; t < 16; t++) {
            int idx = tid + 256 * t;
            int rr = idx >> 5, cc = idx & 31;
            int row = m0 + rr, col = n0 + cc * 4;
            if (row < M && col < Nc) {
                float4 v = *(float4*)(ep + rr * 128 + cc * 4);
                if (bias) {
                    v.x += bias[col]; v.y += bias[col + 1];
                    v.z += bias[col + 2]; v.w += bias[col + 3];
                }
                *(float4*)(C + (size_t)row * Nc + col) = v;
                if (STATS) {
                    ls[0] += v.x; lq[0] += v.x * v.x;
                    ls[1] += v.y; lq[1] += v.y * v.y;
                    ls[2] += v.z; lq[2] += v.z * v.z;
                    ls[3] += v.w; lq[3] += v.w * v.w;
                }
            }
        }
    } else {
#pragma unroll
        for (int t = 0; t < 64; t++) {
            int idx = tid + 256 * t;
            int rr = idx >> 7, cc = idx & 127;
            int row = m0 + rr, col = n0 + cc;
            if (row < M && col < Nc) {
                float v = ep[rr * 128 + cc];
                if (bias) v += bias[col];
                C[(size_t)row * Nc + col] = v;
            }
        }
    }
    if (STATS) {
        // per-thread columns are fixed: cc*4..cc*4+3 with cc = tid&31
        __syncthreads();
        float* st = (float*)sm;          // reuse ep region: 256 floats
        if (tid < 256) st[tid] = 0.f;
        __syncthreads();
        int cb = (tid & 31) * 4;
#pragma unroll
        for (int k = 0; k < 4; k++) {
            atomicAdd(&st[cb + k], ls[k]);
            atomicAdd(&st[128 + cb + k], lq[k]);
        }
        __syncthreads();
        if (tid < 128) {
            atomicAdd(&sums[tid], st[tid]);
            atomicAdd(&sums[Nc + tid], st[128 + tid]);
        }
    }
    if (SDOT) {
        // fused attention-logit partials: this 128-col tile is in one head
        const int lane = tid & 31;
        const int head = (n0 >= 256) ? 1 : 0;
        const int cb = n0 & 255;
        float as[4], ad[4];
#pragma unroll
        for (int k = 0; k < 4; k++) {
            as[k] = a_src[head * 256 + cb + lane * 4 + k];
            ad[k] = a_dst[head * 256 + cb + lane * 4 + k];
        }
        for (int r = wid * 16; r < wid * 16 + 16; r++) {
            int row = m0 + r;
            if (row < M) {
                const float* rp = ep + r * 128 + lane * 4;
                float sv = 0.f, dv = 0.f;
#pragma unroll
                for (int k = 0; k < 4; k++) {
                    sv = fmaf(rp[k], as[k], sv);
                    dv = fmaf(rp[k], ad[k], dv);
                }
#pragma unroll
                for (int o = 16; o; o >>= 1) {
                    sv += __shfl_xor_sync(0xffffffffu, sv, o);
                    dv += __shfl_xor_sync(0xffffffffu, dv, o);
                }
                if (lane == 0) {
                    atomicAdd(&s[2 * row + head], sv);
                    atomicAdd(&d[2 * row + head], dv);
                }
            }
        }
    }
}

__device__ __forceinline__ float4 f4fma(float4 a, float w, float4 acc) {
    acc.x = fmaf(a.x, w, acc.x); acc.y = fmaf(a.y, w, acc.y);
    acc.z = fmaf(a.z, w, acc.z); acc.w = fmaf(a.w, w, acc.w);
    return acc;
}

// ======================= GAT softmax: per-edge weights ======================
__global__ void gat_softmax(const float* __restrict__ s, const float* __restrict__ d,
                            const int* __restrict__ rowptr, const int* __restrict__ csr,
                            float* __restrict__ gw, float* __restrict__ selfw) {
    int warp = (blockIdx.x * blockDim.x + threadIdx.x) >> 5;
    int lane = threadIdx.x & 31;
    if (warp >= NND) return;
    int n = warp;
    int beg = rowptr[n], end = rowptr[n + 1];
    float d0 = d[2 * n], d1 = d[2 * n + 1];
    float self0 = lrelu(s[2 * n] + d0);
    float self1 = lrelu(s[2 * n + 1] + d1);

    float m0 = self0, z0 = 1.f, m1 = self1, z1 = 1.f;
    if (lane != 0) { m0 = -3.4e38f; z0 = 0.f; m1 = -3.4e38f; z1 = 0.f; }
    for (int i = beg + lane; i < end; i += 32) {
        int src = csr[i];
        float a0v = lrelu(s[2 * src] + d0);
        float a1v = lrelu(s[2 * src + 1] + d1);
        float mn0 = fmaxf(m0, a0v);
        z0 = z0 * __expf(m0 - mn0) + __expf(a0v - mn0);
        m0 = mn0;
        float mn1 = fmaxf(m1, a1v);
        z1 = z1 * __expf(m1 - mn1) + __expf(a1v - mn1);
        m1 = mn1;
    }
#pragma unroll
    for (int o = 16; o; o >>= 1) {
        float mo0 = __shfl_xor_sync(0xffffffffu, m0, o);
        float zo0 = __shfl_xor_sync(0xffffffffu, z0, o);
        float mn0 = fmaxf(m0, mo0);
        z0 = z0 * __expf(m0 - mn0) + zo0 * __expf(mo0 - mn0);
        m0 = mn0;
        float mo1 = __shfl_xor_sync(0xffffffffu, m1, o);
        float zo1 = __shfl_xor_sync(0xffffffffu, z1, o);
        float mn1 = fmaxf(m1, mo1);
        z1 = z1 * __expf(m1 - mn1) + zo1 * __expf(mo1 - mn1);
        m1 = mn1;
    }
    float inv0 = 1.f / (z0 + 1e-16f), inv1 = 1.f / (z1 + 1e-16f);

    if (lane == 0) {
        selfw[2 * n]     = __expf(self0 - m0) * inv0;
        selfw[2 * n + 1] = __expf(self1 - m1) * inv1;
    }
    float2* gw2 = (float2*)gw;
    for (int i = beg + lane; i < end; i += 32) {
        int src = csr[i];
        float w0 = __expf(lrelu(s[2 * src] + d0) - m0) * inv0;
        float w1 = __expf(lrelu(s[2 * src + 1] + d1) - m1) * inv1;
        gw2[i] = make_float2(w0, w1);
    }
}

// ======================= GAT gather: weighted aggregation ===================
__global__ void gat_gather(const float* __restrict__ h, const int* __restrict__ rowptr,
                           const int* __restrict__ csr, const float* __restrict__ gw,
                           const float* __restrict__ selfw, const float* __restrict__ bias,
                           float* __restrict__ out) {
    int warp = (blockIdx.x * blockDim.x + threadIdx.x) >> 5;
    int lane = threadIdx.x & 31;
    if (warp >= NND) return;
    int n = warp;
    int beg = rowptr[n], end = rowptr[n + 1];
    const float2* gw2 = (const float2*)gw;

    const float4* h4 = (const float4*)h;
    float4 a0 = {0, 0, 0, 0}, a1 = a0, a2 = a0, a3 = a0;
    {
        float2 sw = ((const float2*)selfw)[n];
        const float4* row = h4 + (size_t)n * 128;
        a0 = f4fma(row[lane], sw.x, a0);
        a1 = f4fma(row[lane + 32], sw.x, a1);
        a2 = f4fma(row[lane + 64], sw.y, a2);
        a3 = f4fma(row[lane + 96], sw.y, a3);
    }
    for (int i = beg; i < end; i++) {
        int src = csr[i];          // uniform broadcast, sequential addresses
        float2 w = gw2[i];         // uniform broadcast, sequential addresses
        const float4* row = h4 + (size_t)src * 128;
        a0 = f4fma(row[lane], w.x, a0);
        a1 = f4fma(row[lane + 32], w.x, a1);
        a2 = f4fma(row[lane + 64], w.y, a2);
        a3 = f4fma(row[lane + 96], w.y, a3);
    }
    const float4* b4 = (const float4*)bias;
    float4 bA = b4[lane], bB = b4[lane + 32];
    float4 r0, r1;
    r0.x = (a0.x + a2.x) * 0.5f + bA.x; r0.y = (a0.y + a2.y) * 0.5f + bA.y;
    r0.z = (a0.z + a2.z) * 0.5f + bA.z; r0.w = (a0.w + a2.w) * 0.5f + bA.w;
    r1.x = (a1.x + a3.x) * 0.5f + bB.x; r1.y = (a1.y + a3.y) * 0.5f + bB.y;
    r1.z = (a1.z + a3.z) * 0.5f + bB.z; r1.w = (a1.w + a3.w) * 0.5f + bB.w;
    float4* o4 = (float4*)out;
    o4[(size_t)n * 64 + lane] = r0;
    o4[(size_t)n * 64 + lane + 32] = r1;
}

// ======================= batch norm =======================
__global__ void bn_stats(const float* __restrict__ x, float* __restrict__ sums,
                         int rows, int C, int rowsPerBlock) {
    int c = threadIdx.x;
    int r0 = blockIdx.x * rowsPerBlock;
    int r1 = min(rows, r0 + rowsPerBlock);
    float s = 0.f, q = 0.f;
    for (int r = r0; r < r1; r++) {
        float v = x[(size_t)r * C + c];
        s += v;
        q += v * v;
    }
    atomicAdd(&sums[c], s);
    atomicAdd(&sums[C + c], q);
}

// apply BN+relu, emit fp16 (GEMM A-operand form); optionally zero s,d
__global__ void bn_apply_h(const float* __restrict__ x, const float* __restrict__ sums,
                           const float* __restrict__ g, const float* __restrict__ b,
                           __half* __restrict__ H, int rows, int C,
                           float* __restrict__ sz, float* __restrict__ dz) {
    size_t i = (size_t)blockIdx.x * blockDim.x + threadIdx.x;
    if (i >= (size_t)rows * C) return;
    if (sz && i < 2 * NND) { sz[i] = 0.f; dz[i] = 0.f; }
    int c = (int)(i % C);
    float mu = sums[c] / rows;
    float var = sums[C + c] / rows - mu * mu;
    float y = g[c] * (x[i] - mu) * rsqrtf(var + 1e-5f) + b[c];
    H[i] = __float2half(fmaxf(y, 0.f));
}

// ======================= launch =======================
extern "C" void kernel_launch(void* const* d_in, const int* in_sizes, int n_in,
                              void* d_out, int out_size) {
    const int*   edge_index = (const int*)d_in[0];
    const float* x      = (const float*)d_in[1];
    const int*   edge_id = (const int*)d_in[2];
    const float* W1     = (const float*)d_in[3];
    const float* a_src1 = (const float*)d_in[4];
    const float* a_dst1 = (const float*)d_in[5];
    const float* b1     = (const float*)d_in[6];
    const float* bn1_g  = (const float*)d_in[7];
    const float* bn1_b  = (const float*)d_in[8];
    const float* W2     = (const float*)d_in[9];
    const float* a_src2 = (const float*)d_in[10];
    const float* a_dst2 = (const float*)d_in[11];
    const float* b2     = (const float*)d_in[12];
    const float* bn2_g  = (const float*)d_in[13];
    const float* bn2_b  = (const float*)d_in[14];
    const float* lw1    = (const float*)d_in[15];
    const float* lb1    = (const float*)d_in[16];
    const float* bn3_g  = (const float*)d_in[17];
    const float* bn3_b  = (const float*)d_in[18];
    const float* lw2    = (const float*)d_in[19];
    const float* lb2    = (const float*)d_in[20];
    const float* bn4_g  = (const float*)d_in[21];
    const float* bn4_b  = (const float*)d_in[22];
    const float* fw     = (const float*)d_in[23];
    const float* fb     = (const float*)d_in[24];
    float* out = (float*)d_out;

    float *h, *feat, *s, *d, *z1, *z2, *sums, *gw, *selfw;
    int *deg, *rowptr, *cursor, *csr;
    __half *xh, *fh, *z1h, *z2h;
    __half *w1th, *w1tl, *w2th, *w2tl, *lw1th, *lw1tl, *lw2th, *lw2tl, *fwth, *fwtl;
    cudaGetSymbolAddress((void**)&h, g_h);
    cudaGetSymbolAddress((void**)&feat, g_feat);
    cudaGetSymbolAddress((void**)&s, g_s);
    cudaGetSymbolAddress((void**)&d, g_d);
    cudaGetSymbolAddress((void**)&z1, g_z1);
    cudaGetSymbolAddress((void**)&z2, g_z2);
    cudaGetSymbolAddress((void**)&sums, g_sums);
    cudaGetSymbolAddress((void**)&gw, g_gw);
    cudaGetSymbolAddress((void**)&selfw, g_selfw);
    cudaGetSymbolAddress((void**)&deg, g_deg);
    cudaGetSymbolAddress((void**)&rowptr, g_rowptr);
    cudaGetSymbolAddress((void**)&cursor, g_cursor);
    cudaGetSymbolAddress((void**)&csr, g_csr);
    cudaGetSymbolAddress((void**)&xh, g_xh);
    cudaGetSymbolAddress((void**)&fh, g_fh);
    cudaGetSymbolAddress((void**)&z1h, g_z1h);
    cudaGetSymbolAddress((void**)&z2h, g_z2h);
    cudaGetSymbolAddress((void**)&w1th, g_w1th);
    cudaGetSymbolAddress((void**)&w1tl, g_w1tl);
    cudaGetSymbolAddress((void**)&w2th, g_w2th);
    cudaGetSymbolAddress((void**)&w2tl, g_w2tl);
    cudaGetSymbolAddress((void**)&lw1th, g_lw1th);
    cudaGetSymbolAddress((void**)&lw1tl, g_lw1tl);
    cudaGetSymbolAddress((void**)&lw2th, g_lw2th);
    cudaGetSymbolAddress((void**)&lw2tl, g_lw2tl);
    cudaGetSymbolAddress((void**)&fwth, g_fwth);
    cudaGetSymbolAddress((void**)&fwtl, g_fwtl);

    cudaFuncSetAttribute(tg_gemm<false, true, false>, cudaFuncAttributeMaxDynamicSharedMemorySize, MG_SMEM);
    cudaFuncSetAttribute(tg_gemm<false, false, false>, cudaFuncAttributeMaxDynamicSharedMemorySize, MG_SMEM);
    cudaFuncSetAttribute(tg_gemm<false, false, true>, cudaFuncAttributeMaxDynamicSharedMemorySize, MG_SMEM);
    cudaFuncSetAttribute(tg_gemm<true, false, true>, cudaFuncAttributeMaxDynamicSharedMemorySize, MG_SMEM);

    const int mt_n = NNDP / 128;   // 391
    const int mt_p = NP / 128;     // 2048

    // ---- prep + GEMM1 placed so GEMM1 is launch index 3 (ncu capture slot) ----
    conv_mat<<<((size_t)NNDP * 576 + 255) / 256, 256>>>(x, xh, s, d, NND, FIN, 576,
                                                        NNDP * 576);                       // 0
    transposeW_split<<<(512 * 576 + 255) / 256, 256>>>(W1, w1th, w1tl, FIN, 512, 512, 576); // 1
    transposeW_split<<<(512 * 256 + 255) / 256, 256>>>(W2, w2th, w2tl, C1, 512, 512, 256);  // 2
    tg_gemm<false, true, false><<<dim3(4, mt_n), 256, MG_SMEM>>>(                           // 3
        xh, w1th, w1tl, nullptr, h, NND, 512, 576, 576, nullptr, nullptr, 0,
        a_src1, a_dst1, s, d, nullptr);

    // ---- remaining prep (independent of GEMM1) ----
    transposeW_rest<<<(128 * 512 + 2 * 128 * 128 + 255) / 256, 256>>>(
        lw1, lw2, fw, lw1th, lw1tl, lw2th, lw2tl, fwth, fwtl);

    // ---- CSR build ----
    zero_i<<<(NND + 255) / 256, 256>>>(deg, NND);
    count_deg<<<(NE + 255) / 256, 256>>>(edge_index, deg);
    scan_kernel<<<1, 1024>>>(deg, rowptr, cursor);
    fill_csr<<<(NE + 255) / 256, 256>>>(edge_index, cursor, csr);

    // ---- GAT layer 1 ----
    gat_softmax<<<(NND * 32 + 255) / 256, 256>>>(s, d, rowptr, csr, gw, selfw);
    gat_gather<<<(NND * 32 + 255) / 256, 256>>>(h, rowptr, csr, gw, selfw, b1, feat);
    zero_f<<<2, 256>>>(sums, 512);
    bn_stats<<<(NND + 511) / 512, 256>>>(feat, sums, NND, C1, 512);
    bn_apply_h<<<(int)(((size_t)NND * C1 + 255) / 256), 256>>>(
        feat, sums, bn1_g, bn1_b, fh, NND, C1, s, d);   // also re-zeroes s,d for layer 2

    // ---- GAT layer 2 ----
    tg_gemm<false, true, false><<<dim3(4, mt_n), 256, MG_SMEM>>>(
        fh, w2th, w2tl, nullptr, h, NND, 512, 256, 256, nullptr, nullptr, 0,
        a_src2, a_dst2, s, d, nullptr);
    gat_softmax<<<(NND * 32 + 255) / 256, 256>>>(s, d, rowptr, csr, gw, selfw);
    gat_gather<<<(NND * 32 + 255) / 256, 256>>>(h, rowptr, csr, gw, selfw, b2, feat);
    zero_f<<<2, 256>>>(sums, 512);
    bn_stats<<<(NND + 511) / 512, 256>>>(feat, sums, NND, C1, 512);
    bn_apply_h<<<(int)(((size_t)NND * C1 + 255) / 256), 256>>>(
        feat, sums, bn2_g, bn2_b, fh, NND, C1, nullptr, nullptr);

    // ---- pair MLP (BN stats fused into GEMM epilogues) ----
    zero_f<<<1, 256>>>(sums, 256);
    tg_gemm<true, false, true><<<dim3(1, mt_p), 256, MG_SMEM>>>(
        fh, lw1th, lw1tl, lb1, z1, NP, C2, 512, C1, edge_id, edge_id + NP, C1,
        nullptr, nullptr, nullptr, nullptr, sums);
    bn_apply_h<<<(int)(((size_t)NP * C2 + 255) / 256), 256>>>(
        z1, sums, bn3_g, bn3_b, z1h, NP, C2, nullptr, nullptr);

    zero_f<<<1, 256>>>(sums, 256);
    tg_gemm<false, false, true><<<dim3(1, mt_p), 256, MG_SMEM>>>(
        z1h, lw2th, lw2tl, lb2, z2, NP, C2, 128, 128, nullptr, nullptr, 0,
        nullptr, nullptr, nullptr, nullptr, sums);
    bn_apply_h<<<(int)(((size_t)NP * C2 + 255) / 256), 256>>>(
        z2, sums, bn4_g, bn4_b, z2h, NP, C2, nullptr, nullptr);

    tg_gemm<false, false, false><<<dim3(1, mt_p), 256, MG_SMEM>>>(
        z2h, fwth, fwtl, fb, out, NP, NC, 128, 128, nullptr, nullptr, 0,
        nullptr, nullptr, nullptr, nullptr, nullptr);
}

// round 16
// speedup vs baseline: 1.6882x; 1.0662x over previous
#include <cuda_runtime.h>
#include <cuda_fp16.h>
#include <mma.h>
#include <cstdint>
#include <math.h>

using namespace nvcuda;

#define NND 50000
#define NNDP 50048          // padded to 128
#define NE  800000
#define NP  262144
#define FIN 572
#define C1  256     // H1
#define C2  128     // H2
#define NC  65

// ======================= scratch =======================
__device__ __half g_h[(size_t)NND * 512];     // post-W features fp16 (values only;
                                              // logits computed fp32 in GEMM epilogue)
__device__ float g_feat[(size_t)NND * C1];
__device__ float g_s[NND * 2];
__device__ float g_d[NND * 2];
__device__ float g_z1[(size_t)NP * C2];
__device__ float g_z2[(size_t)NP * C2];
__device__ float g_sums[512];
__device__ float g_gw[2 * NE];                // per-edge normalized weights (2 heads)
__device__ float g_selfw[2 * NND];            // per-node self-loop weights
__device__ int   g_deg[NND];
__device__ int   g_rowptr[NND + 1];
__device__ int   g_cursor[NND];
__device__ int   g_csr[NE];
// fp16 activation operand arrays (padded rows)
__device__ __half g_xh[(size_t)NNDP * 576];
__device__ __half g_fh[(size_t)NNDP * C1];
__device__ __half g_z1h[(size_t)NP * C2];
__device__ __half g_z2h[(size_t)NP * C2];
// transposed, zero-padded, hi/lo-split fp16 weights [N_pad, kpad]
__device__ __half g_w1th[512 * 576], g_w1tl[512 * 576];
__device__ __half g_w2th[512 * 256], g_w2tl[512 * 256];
__device__ __half g_lw1th[128 * 512], g_lw1tl[128 * 512];
__device__ __half g_lw2th[128 * 128], g_lw2tl[128 * 128];
__device__ __half g_fwth[128 * 128], g_fwtl[128 * 128];

__device__ __forceinline__ float lrelu(float x) { return x > 0.f ? x : 0.2f * x; }

__device__ __forceinline__ void split_w(float v, __half* H, __half* L) {
    __half hi = __float2half(v);
    *H = hi;
    *L = __float2half(v - __half2float(hi));
}

__global__ void zero_i(int* p, int n) {
    int i = blockIdx.x * blockDim.x + threadIdx.x;
    if (i < n) p[i] = 0;
}
__global__ void zero_f(float* p, int n) {
    int i = blockIdx.x * blockDim.x + threadIdx.x;
    if (i < n) p[i] = 0.f;
}

// X [M,K] fp32 -> fp16 [Mpad,kpad] zero padded; also zeroes s,d (2*NND)
__global__ void conv_mat(const float* __restrict__ X, __half* __restrict__ H,
                         float* __restrict__ s, float* __restrict__ d,
                         int M, int K, int kpad, int total) {
    int i = blockIdx.x * blockDim.x + threadIdx.x;
    if (i >= total) return;
    if (i < 2 * NND) { s[i] = 0.f; d[i] = 0.f; }
    int row = i / kpad, k = i - row * kpad;
    H[i] = __float2half((row < M && k < K) ? X[(size_t)row * K + k] : 0.f);
}

// Wt[n*kpad+k] = W[k*N+n], split to fp16 hi/lo, zero padded
__global__ void transposeW_split(const float* __restrict__ W, __half* __restrict__ H,
                                 __half* __restrict__ L, int K, int N, int rows,
                                 int kpad) {
    int i = blockIdx.x * blockDim.x + threadIdx.x;
    int tot = rows * kpad;
    if (i >= tot) return;
    int n = i / kpad, k = i - n * kpad;
    float v = (k < K && n < N) ? W[(size_t)k * N + n] : 0.f;
    split_w(v, H + i, L + i);
}

// fused: lw1 + lw2 + fw split-transposes in one launch
__global__ void transposeW_rest(const float* __restrict__ lw1,
                                const float* __restrict__ lw2, const float* __restrict__ fw,
                                __half* __restrict__ H1, __half* __restrict__ L1,
                                __half* __restrict__ H2, __half* __restrict__ L2,
                                __half* __restrict__ HF, __half* __restrict__ LF) {
    int i = blockIdx.x * blockDim.x + threadIdx.x;
    if (i < 128 * 512) {
        int n = i >> 9, k = i & 511;
        split_w(lw1[(size_t)k * C2 + n], H1 + i, L1 + i);
    } else if (i < 128 * 512 + 128 * 128) {
        int j = i - 128 * 512;
        int n = j >> 7, k = j & 127;
        split_w(lw2[(size_t)k * C2 + n], H2 + j, L2 + j);
    } else if (i < 128 * 512 + 2 * 128 * 128) {
        int j = i - 128 * 512 - 128 * 128;
        int n = j >> 7, k = j & 127;
        float v = (n < NC) ? fw[(size_t)k * NC + n] : 0.f;
        split_w(v, HF + j, LF + j);
    }
}

// ======================= CSR build =======================
__global__ void count_deg(const int* __restrict__ ei, int* __restrict__ deg) {
    int e = blockIdx.x * blockDim.x + threadIdx.x;
    if (e < NE) atomicAdd(&deg[ei[NE + e]], 1);
}

__global__ void scan_kernel(const int* __restrict__ deg, int* __restrict__ rowptr,
                            int* __restrict__ cursor) {
    __shared__ int sh[1024];
    __shared__ int carry_s;
    int t = threadIdx.x;
    if (t == 0) { carry_s = 0; rowptr[0] = 0; }
    __syncthreads();
    for (int base = 0; base < NND; base += 1024) {
        int v = (base + t < NND) ? deg[base + t] : 0;
        sh[t] = v;
        __syncthreads();
        for (int off = 1; off < 1024; off <<= 1) {
            int add = (t >= off) ? sh[t - off] : 0;
            __syncthreads();
            sh[t] += add;
            __syncthreads();
        }
        int incl = sh[t];
        int carry = carry_s;
        if (base + t < NND) {
            rowptr[base + t + 1] = carry + incl;
            cursor[base + t]     = carry + incl - v;
        }
        __syncthreads();
        if (t == 1023) carry_s = carry + incl;
        __syncthreads();
    }
}

__global__ void fill_csr(const int* __restrict__ ei, int* __restrict__ cursor,
                         int* __restrict__ csr) {
    int e = blockIdx.x * blockDim.x + threadIdx.x;
    if (e < NE) {
        int dn = ei[NE + e];
        int pos = atomicAdd(&cursor[dn], 1);
        csr[pos] = ei[e];
    }
}

// ======================= fp16x2 (split-B) wmma GEMM =============
// CTA 128x128, 8 warps (2x4), warp tile 64x32, BK=32, cp.async 2-stage.
// SDOT: fused attention-logit partial dots (fp32, from epilogue SMEM).
// STATS: fused BN column stats (Nc==128, grid.x==1, M mult of 128).
// HOUT: write fp16 h instead of fp32 C (Nc mult of 4).
#define TROW 40                   // padded SMEM row (halves) -> 80 B
#define TILE_B (128 * TROW * 2)   // 10240 B per tile
#define BUF_B  (3 * TILE_B)       // A + Bh + Bl = 30720 B
#define MG_SMEM 65536             // 2 stages (61440) | epilogue 64KB union

__device__ __forceinline__ uint32_t smem_u32(const void* p) {
    uint32_t a;
    asm("{ .reg .u64 t; cvta.to.shared.u64 t, %1; cvt.u32.u64 %0, t; }"
        : "=r"(a) : "l"(p));
    return a;
}
__device__ __forceinline__ void cpa16(void* dst, const void* src) {
    asm volatile("cp.async.cg.shared.global [%0], [%1], 16;"
                 :: "r"(smem_u32(dst)), "l"(src));
}

template <bool GATHER, bool SDOT, bool STATS, bool HOUT>
__global__ void __launch_bounds__(256, 2) tg_gemm(
    const __half* __restrict__ A,
    const __half* __restrict__ Bh, const __half* __restrict__ Bl,
    const float* __restrict__ bias, float* __restrict__ C,
    __half* __restrict__ Ch,
    int M, int Nc, int kpad, int strideA,
    const int* __restrict__ id0, const int* __restrict__ id1, int baseW,
    const float* __restrict__ a_src, const float* __restrict__ a_dst,
    float* __restrict__ s, float* __restrict__ d,
    float* __restrict__ sums) {
    extern __shared__ char sm[];
    __shared__ int sid0[128], sid1[128];
    float* ep = (float*)sm;

    const int tid = threadIdx.x;
    const int wid = tid >> 5;
    const int wm = wid >> 2;
    const int wn = wid & 3;
    const int m0 = blockIdx.y * 128;
    const int n0 = blockIdx.x * 128;
    const int chunks = kpad >> 5;
    const int lr = tid >> 2;     // 0..63
    const int lc = tid & 3;      // 16B slot

    if (GATHER) {
        if (tid < 128) {
            sid0[tid] = id0[m0 + tid];
            sid1[tid] = id1[m0 + tid];
        }
        __syncthreads();
    }

    wmma::fragment<wmma::accumulator, 16, 16, 16, float> acc[4][2];
#pragma unroll
    for (int i = 0; i < 4; i++)
#pragma unroll
        for (int j = 0; j < 2; j++) wmma::fill_fragment(acc[i][j], 0.f);

    auto load_chunk = [&](int kt, int buf) {
        const int k0 = kt << 5;
        char* base = sm + buf * BUF_B;
        int halfsel = 0, kc = k0 + lc * 8;
        if (GATHER) {
            halfsel = (k0 >= baseW) ? 1 : 0;
            kc = k0 - halfsel * baseW + lc * 8;
        }
#pragma unroll
        for (int it = 0; it < 2; it++) {
            int rr = lr + it * 64;
            size_t aoff;
            if (GATHER) {
                int nid = halfsel ? sid1[rr] : sid0[rr];
                aoff = (size_t)nid * strideA + kc;
            } else {
                aoff = (size_t)(m0 + rr) * strideA + kc;
            }
            int dst = rr * (TROW * 2) + lc * 16;
            cpa16(base + dst, A + aoff);
            size_t boff = (size_t)(n0 + rr) * kpad + k0 + lc * 8;
            cpa16(base + TILE_B + dst, Bh + boff);
            cpa16(base + 2 * TILE_B + dst, Bl + boff);
        }
    };

    load_chunk(0, 0);
    asm volatile("cp.async.commit_group;");

    for (int kt = 0; kt < chunks; kt++) {
        if (kt + 1 < chunks) {
            load_chunk(kt + 1, (kt + 1) & 1);
            asm volatile("cp.async.commit_group;");
            asm volatile("cp.async.wait_group 1;");
        } else {
            asm volatile("cp.async.wait_group 0;");
        }
        __syncthreads();
        char* base = sm + (kt & 1) * BUF_B;
        const __half* sA  = (const __half*)(base);
        const __half* sBh = (const __half*)(base + TILE_B);
        const __half* sBl = (const __half*)(base + 2 * TILE_B);
#pragma unroll
        for (int ks = 0; ks < 32; ks += 16) {
            wmma::fragment<wmma::matrix_a, 16, 16, 16, __half, wmma::row_major> fa[4];
#pragma unroll
            for (int i = 0; i < 4; i++)
                wmma::load_matrix_sync(fa[i], sA + (wm * 64 + i * 16) * TROW + ks, TROW);
#pragma unroll
            for (int j = 0; j < 2; j++) {
                wmma::fragment<wmma::matrix_b, 16, 16, 16, __half, wmma::col_major> fbh, fbl;
                wmma::load_matrix_sync(fbh, sBh + (wn * 32 + j * 16) * TROW + ks, TROW);
                wmma::load_matrix_sync(fbl, sBl + (wn * 32 + j * 16) * TROW + ks, TROW);
#pragma unroll
                for (int i = 0; i < 4; i++) {
                    wmma::mma_sync(acc[i][j], fa[i], fbh, acc[i][j]);
                    wmma::mma_sync(acc[i][j], fa[i], fbl, acc[i][j]);
                }
            }
        }
        __syncthreads();
    }

    // ---- epilogue: stage in SMEM, guarded global write ----
#pragma unroll
    for (int i = 0; i < 4; i++)
#pragma unroll
        for (int j = 0; j < 2; j++)
            wmma::store_matrix_sync(ep + (wm * 64 + i * 16) * 128 + wn * 32 + j * 16,
                                    acc[i][j], 128, wmma::mem_row_major);
    __syncthreads();
    float ls[4] = {0, 0, 0, 0}, lq[4] = {0, 0, 0, 0};
    if (HOUT) {
        // fp16 output (values path); logits later from fp32 ep
#pragma unroll
        for (int t = 0; t < 16; t++) {
            int idx = tid + 256 * t;
            int rr = idx >> 5, cc = idx & 31;
            int row = m0 + rr, col = n0 + cc * 4;
            if (row < M && col < Nc) {
                float4 v = *(float4*)(ep + rr * 128 + cc * 4);
                if (bias) {
                    v.x += bias[col]; v.y += bias[col + 1];
                    v.z += bias[col + 2]; v.w += bias[col + 3];
                }
                __half2 p0 = __floats2half2_rn(v.x, v.y);
                __half2 p1 = __floats2half2_rn(v.z, v.w);
                uint2 pk = make_uint2(*(uint32_t*)&p0, *(uint32_t*)&p1);
                *(uint2*)(Ch + (size_t)row * Nc + col) = pk;
            }
        }
    } else if ((Nc & 3) == 0) {
#pragma unroll
        for (int t = 0; t < 16; t++) {
            int idx = tid + 256 * t;
            int rr = idx >> 5, cc = idx & 31;
            int row = m0 + rr, col = n0 + cc * 4;
            if (row < M && col < Nc) {
                float4 v = *(float4*)(ep + rr * 128 + cc * 4);
                if (bias) {
                    v.x += bias[col]; v.y += bias[col + 1];
                    v.z += bias[col + 2]; v.w += bias[col + 3];
                }
                *(float4*)(C + (size_t)row * Nc + col) = v;
                if (STATS) {
                    ls[0] += v.x; lq[0] += v.x * v.x;
                    ls[1] += v.y; lq[1] += v.y * v.y;
                    ls[2] += v.z; lq[2] += v.z * v.z;
                    ls[3] += v.w; lq[3] += v.w * v.w;
                }
            }
        }
    } else {
#pragma unroll
        for (int t = 0; t < 64; t++) {
            int idx = tid + 256 * t;
            int rr = idx >> 7, cc = idx & 127;
            int row = m0 + rr, col = n0 + cc;
            if (row < M && col < Nc) {
                float v = ep[rr * 128 + cc];
                if (bias) v += bias[col];
                C[(size_t)row * Nc + col] = v;
            }
        }
    }
    if (STATS) {
        __syncthreads();
        float* st = (float*)sm;          // reuse ep region: 256 floats
        if (tid < 256) st[tid] = 0.f;
        __syncthreads();
        int cb = (tid & 31) * 4;
#pragma unroll
        for (int k = 0; k < 4; k++) {
            atomicAdd(&st[cb + k], ls[k]);
            atomicAdd(&st[128 + cb + k], lq[k]);
        }
        __syncthreads();
        if (tid < 128) {
            atomicAdd(&sums[tid], st[tid]);
            atomicAdd(&sums[Nc + tid], st[128 + tid]);
        }
    }
    if (SDOT) {
        // fused attention-logit partials from fp32 ep (exact logits)
        const int lane = tid & 31;
        const int head = (n0 >= 256) ? 1 : 0;
        const int cb = n0 & 255;
        float as[4], ad[4];
#pragma unroll
        for (int k = 0; k < 4; k++) {
            as[k] = a_src[head * 256 + cb + lane * 4 + k];
            ad[k] = a_dst[head * 256 + cb + lane * 4 + k];
        }
        for (int r = wid * 16; r < wid * 16 + 16; r++) {
            int row = m0 + r;
            if (row < M) {
                const float* rp = ep + r * 128 + lane * 4;
                float sv = 0.f, dv = 0.f;
#pragma unroll
                for (int k = 0; k < 4; k++) {
                    sv = fmaf(rp[k], as[k], sv);
                    dv = fmaf(rp[k], ad[k], dv);
                }
#pragma unroll
                for (int o = 16; o; o >>= 1) {
                    sv += __shfl_xor_sync(0xffffffffu, sv, o);
                    dv += __shfl_xor_sync(0xffffffffu, dv, o);
                }
                if (lane == 0) {
                    atomicAdd(&s[2 * row + head], sv);
                    atomicAdd(&d[2 * row + head], dv);
                }
            }
        }
    }
}

// ======================= GAT softmax: per-edge weights ======================
__global__ void gat_softmax(const float* __restrict__ s, const float* __restrict__ d,
                            const int* __restrict__ rowptr, const int* __restrict__ csr,
                            float* __restrict__ gw, float* __restrict__ selfw) {
    int warp = (blockIdx.x * blockDim.x + threadIdx.x) >> 5;
    int lane = threadIdx.x & 31;
    if (warp >= NND) return;
    int n = warp;
    int beg = rowptr[n], end = rowptr[n + 1];
    float d0 = d[2 * n], d1 = d[2 * n + 1];
    float self0 = lrelu(s[2 * n] + d0);
    float self1 = lrelu(s[2 * n + 1] + d1);

    float m0 = self0, z0 = 1.f, m1 = self1, z1 = 1.f;
    if (lane != 0) { m0 = -3.4e38f; z0 = 0.f; m1 = -3.4e38f; z1 = 0.f; }
    for (int i = beg + lane; i < end; i += 32) {
        int src = csr[i];
        float a0v = lrelu(s[2 * src] + d0);
        float a1v = lrelu(s[2 * src + 1] + d1);
        float mn0 = fmaxf(m0, a0v);
        z0 = z0 * __expf(m0 - mn0) + __expf(a0v - mn0);
        m0 = mn0;
        float mn1 = fmaxf(m1, a1v);
        z1 = z1 * __expf(m1 - mn1) + __expf(a1v - mn1);
        m1 = mn1;
    }
#pragma unroll
    for (int o = 16; o; o >>= 1) {
        float mo0 = __shfl_xor_sync(0xffffffffu, m0, o);
        float zo0 = __shfl_xor_sync(0xffffffffu, z0, o);
        float mn0 = fmaxf(m0, mo0);
        z0 = z0 * __expf(m0 - mn0) + zo0 * __expf(mo0 - mn0);
        m0 = mn0;
        float mo1 = __shfl_xor_sync(0xffffffffu, m1, o);
        float zo1 = __shfl_xor_sync(0xffffffffu, z1, o);
        float mn1 = fmaxf(m1, mo1);
        z1 = z1 * __expf(m1 - mn1) + zo1 * __expf(mo1 - mn1);
        m1 = mn1;
    }
    float inv0 = 1.f / (z0 + 1e-16f), inv1 = 1.f / (z1 + 1e-16f);

    if (lane == 0) {
        selfw[2 * n]     = __expf(self0 - m0) * inv0;
        selfw[2 * n + 1] = __expf(self1 - m1) * inv1;
    }
    float2* gw2 = (float2*)gw;
    for (int i = beg + lane; i < end; i += 32) {
        int src = csr[i];
        float w0 = __expf(lrelu(s[2 * src] + d0) - m0) * inv0;
        float w1 = __expf(lrelu(s[2 * src + 1] + d1) - m1) * inv1;
        gw2[i] = make_float2(w0, w1);
    }
}

// accumulate 8 halves (uint4) * w into 8 floats
__device__ __forceinline__ void h8fma(uint4 v, float w, float* a) {
    const __half2* hp = (const __half2*)&v;
#pragma unroll
    for (int i = 0; i < 4; i++) {
        float2 f = __half22float2(hp[i]);
        a[2 * i]     = fmaf(f.x, w, a[2 * i]);
        a[2 * i + 1] = fmaf(f.y, w, a[2 * i + 1]);
    }
}

// ======================= GAT gather: weighted aggregation (h fp16) ==========
__global__ void gat_gather(const __half* __restrict__ h, const int* __restrict__ rowptr,
                           const int* __restrict__ csr, const float* __restrict__ gw,
                           const float* __restrict__ selfw, const float* __restrict__ bias,
                           float* __restrict__ out) {
    int warp = (blockIdx.x * blockDim.x + threadIdx.x) >> 5;
    int lane = threadIdx.x & 31;
    if (warp >= NND) return;
    int n = warp;
    int beg = rowptr[n], end = rowptr[n + 1];
    const float2* gw2 = (const float2*)gw;

    // lane holds 8 chans of head0 + 8 chans of head1 (uint4 = 8 halves)
    const uint4* h4 = (const uint4*)h;   // 64 uint4 per 512-half row
    float a0[8] = {0, 0, 0, 0, 0, 0, 0, 0};
    float a1[8] = {0, 0, 0, 0, 0, 0, 0, 0};
    {
        float2 sw = ((const float2*)selfw)[n];
        const uint4* row = h4 + (size_t)n * 64;
        h8fma(row[lane], sw.x, a0);
        h8fma(row[lane + 32], sw.y, a1);
    }
    for (int i = beg; i < end; i++) {
        int src = csr[i];          // uniform broadcast, sequential addresses
        float2 w = gw2[i];         // uniform broadcast, sequential addresses
        const uint4* row = h4 + (size_t)src * 64;
        h8fma(row[lane], w.x, a0);
        h8fma(row[lane + 32], w.y, a1);
    }
    // mean over heads + bias; out channels 8*lane .. 8*lane+7
    const float4* b4 = (const float4*)bias;
    float4 bA = b4[2 * lane], bB = b4[2 * lane + 1];
    float4 r0, r1;
    r0.x = (a0[0] + a1[0]) * 0.5f + bA.x; r0.y = (a0[1] + a1[1]) * 0.5f + bA.y;
    r0.z = (a0[2] + a1[2]) * 0.5f + bA.z; r0.w = (a0[3] + a1[3]) * 0.5f + bA.w;
    r1.x = (a0[4] + a1[4]) * 0.5f + bB.x; r1.y = (a0[5] + a1[5]) * 0.5f + bB.y;
    r1.z = (a0[6] + a1[6]) * 0.5f + bB.z; r1.w = (a0[7] + a1[7]) * 0.5f + bB.w;
    float4* o4 = (float4*)out;
    o4[(size_t)n * 64 + 2 * lane] = r0;
    o4[(size_t)n * 64 + 2 * lane + 1] = r1;
}

// ======================= batch norm =======================
__global__ void bn_stats(const float* __restrict__ x, float* __restrict__ sums,
                         int rows, int C, int rowsPerBlock) {
    int c = threadIdx.x;
    int r0 = blockIdx.x * rowsPerBlock;
    int r1 = min(rows, r0 + rowsPerBlock);
    float s = 0.f, q = 0.f;
    for (int r = r0; r < r1; r++) {
        float v = x[(size_t)r * C + c];
        s += v;
        q += v * v;
    }
    atomicAdd(&sums[c], s);
    atomicAdd(&sums[C + c], q);
}

// apply BN+relu, emit fp16 (GEMM A-operand form); optionally zero s,d
__global__ void bn_apply_h(const float* __restrict__ x, const float* __restrict__ sums,
                           const float* __restrict__ g, const float* __restrict__ b,
                           __half* __restrict__ H, int rows, int C,
                           float* __restrict__ sz, float* __restrict__ dz) {
    size_t i = (size_t)blockIdx.x * blockDim.x + threadIdx.x;
    if (i >= (size_t)rows * C) return;
    if (sz && i < 2 * NND) { sz[i] = 0.f; dz[i] = 0.f; }
    int c = (int)(i % C);
    float mu = sums[c] / rows;
    float var = sums[C + c] / rows - mu * mu;
    float y = g[c] * (x[i] - mu) * rsqrtf(var + 1e-5f) + b[c];
    H[i] = __float2half(fmaxf(y, 0.f));
}

// ======================= launch =======================
extern "C" void kernel_launch(void* const* d_in, const int* in_sizes, int n_in,
                              void* d_out, int out_size) {
    const int*   edge_index = (const int*)d_in[0];
    const float* x      = (const float*)d_in[1];
    const int*   edge_id = (const int*)d_in[2];
    const float* W1     = (const float*)d_in[3];
    const float* a_src1 = (const float*)d_in[4];
    const float* a_dst1 = (const float*)d_in[5];
    const float* b1     = (const float*)d_in[6];
    const float* bn1_g  = (const float*)d_in[7];
    const float* bn1_b  = (const float*)d_in[8];
    const float* W2     = (const float*)d_in[9];
    const float* a_src2 = (const float*)d_in[10];
    const float* a_dst2 = (const float*)d_in[11];
    const float* b2     = (const float*)d_in[12];
    const float* bn2_g  = (const float*)d_in[13];
    const float* bn2_b  = (const float*)d_in[14];
    const float* lw1    = (const float*)d_in[15];
    const float* lb1    = (const float*)d_in[16];
    const float* bn3_g  = (const float*)d_in[17];
    const float* bn3_b  = (const float*)d_in[18];
    const float* lw2    = (const float*)d_in[19];
    const float* lb2    = (const float*)d_in[20];
    const float* bn4_g  = (const float*)d_in[21];
    const float* bn4_b  = (const float*)d_in[22];
    const float* fw     = (const float*)d_in[23];
    const float* fb     = (const float*)d_in[24];
    float* out = (float*)d_out;

    float *feat, *s, *d, *z1, *z2, *sums, *gw, *selfw;
    int *deg, *rowptr, *cursor, *csr;
    __half *h, *xh, *fh, *z1h, *z2h;
    __half *w1th, *w1tl, *w2th, *w2tl, *lw1th, *lw1tl, *lw2th, *lw2tl, *fwth, *fwtl;
    cudaGetSymbolAddress((void**)&h, g_h);
    cudaGetSymbolAddress((void**)&feat, g_feat);
    cudaGetSymbolAddress((void**)&s, g_s);
    cudaGetSymbolAddress((void**)&d, g_d);
    cudaGetSymbolAddress((void**)&z1, g_z1);
    cudaGetSymbolAddress((void**)&z2, g_z2);
    cudaGetSymbolAddress((void**)&sums, g_sums);
    cudaGetSymbolAddress((void**)&gw, g_gw);
    cudaGetSymbolAddress((void**)&selfw, g_selfw);
    cudaGetSymbolAddress((void**)&deg, g_deg);
    cudaGetSymbolAddress((void**)&rowptr, g_rowptr);
    cudaGetSymbolAddress((void**)&cursor, g_cursor);
    cudaGetSymbolAddress((void**)&csr, g_csr);
    cudaGetSymbolAddress((void**)&xh, g_xh);
    cudaGetSymbolAddress((void**)&fh, g_fh);
    cudaGetSymbolAddress((void**)&z1h, g_z1h);
    cudaGetSymbolAddress((void**)&z2h, g_z2h);
    cudaGetSymbolAddress((void**)&w1th, g_w1th);
    cudaGetSymbolAddress((void**)&w1tl, g_w1tl);
    cudaGetSymbolAddress((void**)&w2th, g_w2th);
    cudaGetSymbolAddress((void**)&w2tl, g_w2tl);
    cudaGetSymbolAddress((void**)&lw1th, g_lw1th);
    cudaGetSymbolAddress((void**)&lw1tl, g_lw1tl);
    cudaGetSymbolAddress((void**)&lw2th, g_lw2th);
    cudaGetSymbolAddress((void**)&lw2tl, g_lw2tl);
    cudaGetSymbolAddress((void**)&fwth, g_fwth);
    cudaGetSymbolAddress((void**)&fwtl, g_fwtl);

    cudaFuncSetAttribute(tg_gemm<false, true, false, true>, cudaFuncAttributeMaxDynamicSharedMemorySize, MG_SMEM);
    cudaFuncSetAttribute(tg_gemm<true, false, true, false>, cudaFuncAttributeMaxDynamicSharedMemorySize, MG_SMEM);
    cudaFuncSetAttribute(tg_gemm<false, false, true, false>, cudaFuncAttributeMaxDynamicSharedMemorySize, MG_SMEM);
    cudaFuncSetAttribute(tg_gemm<false, false, false, false>, cudaFuncAttributeMaxDynamicSharedMemorySize, MG_SMEM);

    const int mt_n = NNDP / 128;   // 391
    const int mt_p = NP / 128;     // 2048

    // ---- prep + GEMM1 placed so GEMM1 is launch index 3 (ncu capture slot) ----
    conv_mat<<<((size_t)NNDP * 576 + 255) / 256, 256>>>(x, xh, s, d, NND, FIN, 576,
                                                        NNDP * 576);                       // 0
    transposeW_split<<<(512 * 576 + 255) / 256, 256>>>(W1, w1th, w1tl, FIN, 512, 512, 576); // 1
    transposeW_split<<<(512 * 256 + 255) / 256, 256>>>(W2, w2th, w2tl, C1, 512, 512, 256);  // 2
    tg_gemm<false, true, false, true><<<dim3(4, mt_n), 256, MG_SMEM>>>(                     // 3
        xh, w1th, w1tl, nullptr, nullptr, h, NND, 512, 576, 576, nullptr, nullptr, 0,
        a_src1, a_dst1, s, d, nullptr);

    // ---- remaining prep (independent of GEMM1) ----
    transposeW_rest<<<(128 * 512 + 2 * 128 * 128 + 255) / 256, 256>>>(
        lw1, lw2, fw, lw1th, lw1tl, lw2th, lw2tl, fwth, fwtl);

    // ---- CSR build ----
    zero_i<<<(NND + 255) / 256, 256>>>(deg, NND);
    count_deg<<<(NE + 255) / 256, 256>>>(edge_index, deg);
    scan_kernel<<<1, 1024>>>(deg, rowptr, cursor);
    fill_csr<<<(NE + 255) / 256, 256>>>(edge_index, cursor, csr);

    // ---- GAT layer 1 ----
    gat_softmax<<<(NND * 32 + 255) / 256, 256>>>(s, d, rowptr, csr, gw, selfw);
    gat_gather<<<(NND * 32 + 255) / 256, 256>>>(h, rowptr, csr, gw, selfw, b1, feat);
    zero_f<<<2, 256>>>(sums, 512);
    bn_stats<<<(NND + 511) / 512, 256>>>(feat, sums, NND, C1, 512);
    bn_apply_h<<<(int)(((size_t)NND * C1 + 255) / 256), 256>>>(
        feat, sums, bn1_g, bn1_b, fh, NND, C1, s, d);   // also re-zeroes s,d for layer 2

    // ---- GAT layer 2 ----
    tg_gemm<false, true, false, true><<<dim3(4, mt_n), 256, MG_SMEM>>>(
        fh, w2th, w2tl, nullptr, nullptr, h, NND, 512, 256, 256, nullptr, nullptr, 0,
        a_src2, a_dst2, s, d, nullptr);
    gat_softmax<<<(NND * 32 + 255) / 256, 256>>>(s, d, rowptr, csr, gw, selfw);
    gat_gather<<<(NND * 32 + 255) / 256, 256>>>(h, rowptr, csr, gw, selfw, b2, feat);
    zero_f<<<2, 256>>>(sums, 512);
    bn_stats<<<(NND + 511) / 512, 256>>>(feat, sums, NND, C1, 512);
    bn_apply_h<<<(int)(((size_t)NND * C1 + 255) / 256), 256>>>(
        feat, sums, bn2_g, bn2_b, fh, NND, C1, nullptr, nullptr);

    // ---- pair MLP (BN stats fused into GEMM epilogues) ----
    zero_f<<<1, 256>>>(sums, 256);
    tg_gemm<true, false, true, false><<<dim3(1, mt_p), 256, MG_SMEM>>>(
        fh, lw1th, lw1tl, lb1, z1, nullptr, NP, C2, 512, C1, edge_id, edge_id + NP, C1,
        nullptr, nullptr, nullptr, nullptr, sums);
    bn_apply_h<<<(int)(((size_t)NP * C2 + 255) / 256), 256>>>(
        z1, sums, bn3_g, bn3_b, z1h, NP, C2, nullptr, nullptr);

    zero_f<<<1, 256>>>(sums, 256);
    tg_gemm<false, false, true, false><<<dim3(1, mt_p), 256, MG_SMEM>>>(
        z1h, lw2th, lw2tl, lb2, z2, nullptr, NP, C2, 128, 128, nullptr, nullptr, 0,
        nullptr, nullptr, nullptr, nullptr, sums);
    bn_apply_h<<<(int)(((size_t)NP * C2 + 255) / 256), 256>>>(
        z2, sums, bn4_g, bn4_b, z2h, NP, C2, nullptr, nullptr);

    tg_gemm<false, false, false, false><<<dim3(1, mt_p), 256, MG_SMEM>>>(
        z2h, fwth, fwtl, fb, out, nullptr, NP, NC, 128, 128, nullptr, nullptr, 0,
        nullptr, nullptr, nullptr, nullptr, nullptr);
}